// round 11
// baseline (speedup 1.0000x reference)
#include <cuda_runtime.h>

// ---------------------------------------------------------------------------
// Problem constants (fixed shapes from setup_inputs)
// ---------------------------------------------------------------------------
#define NB   4
#define CIN  256          // CH == CL == 256
#define CCC  64           // compressed channels
#define HH   128
#define WW   128
#define HWX  (HH*WW)      // 16384
#define H2   64
#define W2   64
#define HW2  (H2*W2)      // 4096

// ---------------------------------------------------------------------------
// Device-global scratch (no cudaMalloc allowed)
// ---------------------------------------------------------------------------
__device__ float g_chf  [NB*CCC*HWX];   // 16 MB
__device__ float g_chf2 [NB*CCC*HWX];   // 16 MB
__device__ float g_clf  [NB*CCC*HW2];   // 4 MB
__device__ float g_mhh  [NB*9 *HWX];    // mask_hr_hr -> mask_hr (in-place add)
__device__ float g_sm9  [NB*9 *HWX];    // softmax scratch (k=3 masks)
__device__ float g_mlh  [NB*25*HWX];    // mask_lr_hr -> mask_lr (in-place add)
__device__ float g_sm25 [NB*25*HWX];    // softmax(mask_lr_hr)
__device__ float g_mlll [NB*25*HW2];    // enc(clf)
__device__ float g_e2clf[NB*9 *HW2];    // enc2(clf)

// ---------------------------------------------------------------------------
// conv1x1 as SGEMM: Y[n][oc][p] = b[oc] + sum_c W[oc][c] * X[n][c][p]
// M=64, K=256; BN=256 pixels, BK=16; thread tile 8x8 (8 oc x 8 pixels)
// ---------------------------------------------------------------------------
__global__ void __launch_bounds__(256) conv1x1_kernel(
    const float* __restrict__ X, const float* __restrict__ Wt,
    const float* __restrict__ Bi, float* __restrict__ Y, int P)
{
    __shared__ float Ws[16][64];
    __shared__ float Xs[16][256];
    const int n  = blockIdx.z;
    const int p0 = blockIdx.x * 256;
    const int tid = threadIdx.x;
    const int tx = tid & 31;   // pixel group (8 px each)
    const int ty = tid >> 5;   // oc group (8 oc each)
    const float* Xn = X + (size_t)n * CIN * P;

    float acc[8][8];
#pragma unroll
    for (int i = 0; i < 8; i++)
#pragma unroll
        for (int j = 0; j < 8; j++) acc[i][j] = 0.f;

    for (int k0 = 0; k0 < CIN; k0 += 16) {
        // load 16x64 weight tile
#pragma unroll
        for (int i = 0; i < 4; i++) {
            int idx = i * 256 + tid;
            int kk = idx >> 6, mm = idx & 63;
            Ws[kk][mm] = Wt[mm * CIN + k0 + kk];
        }
        // load 16x256 activation tile (float4, coalesced)
#pragma unroll
        for (int i = 0; i < 4; i++) {
            int idx = i * 256 + tid;
            int kk = idx >> 6;
            int pp = (idx & 63) << 2;
            *(float4*)&Xs[kk][pp] =
                *(const float4*)&Xn[(size_t)(k0 + kk) * P + p0 + pp];
        }
        __syncthreads();
#pragma unroll
        for (int k = 0; k < 16; k++) {
            float rw[8], rx[8];
            *(float4*)&rw[0] = *(float4*)&Ws[k][ty * 8];
            *(float4*)&rw[4] = *(float4*)&Ws[k][ty * 8 + 4];
            *(float4*)&rx[0] = *(float4*)&Xs[k][tx * 8];
            *(float4*)&rx[4] = *(float4*)&Xs[k][tx * 8 + 4];
#pragma unroll
            for (int i = 0; i < 8; i++)
#pragma unroll
                for (int j = 0; j < 8; j++)
                    acc[i][j] += rw[i] * rx[j];
        }
        __syncthreads();
    }

#pragma unroll
    for (int i = 0; i < 8; i++) {
        int oc = ty * 8 + i;
        float bv = Bi[oc];
        size_t base = ((size_t)n * CCC + oc) * P + p0 + tx * 8;
        float4 v0 = make_float4(acc[i][0]+bv, acc[i][1]+bv, acc[i][2]+bv, acc[i][3]+bv);
        float4 v1 = make_float4(acc[i][4]+bv, acc[i][5]+bv, acc[i][6]+bv, acc[i][7]+bv);
        *(float4*)&Y[base]     = v0;
        *(float4*)&Y[base + 4] = v1;
    }
}

// ---------------------------------------------------------------------------
// conv3x3, pad=1, Cin=64, Cout=K2 (9 or 25).
// blockDim(32,4); each thread produces XPT consecutive x-pixels in one row.
// tile = full row width (32*XPT == Wi) x 4 rows, +1 halo each side.
// ---------------------------------------------------------------------------
template<int K2, int XPT>
__global__ void __launch_bounds__(128) conv3x3_kernel(
    const float* __restrict__ X, const float* __restrict__ Wt,
    const float* __restrict__ Bi, float* __restrict__ Y,
    int Hi, int Wi)
{
    const int TW = 32 * XPT;          // == Wi
    const int n  = blockIdx.z;
    const int y0 = blockIdx.y * 4;
    const int tx = threadIdx.x, ty = threadIdx.y;
    const int tid = ty * 32 + tx;

    __shared__ float ws[K2 * 9];
    __shared__ float tile[6][32 * XPT + 8];

    float acc[K2][XPT];
#pragma unroll
    for (int o = 0; o < K2; o++)
#pragma unroll
        for (int j = 0; j < XPT; j++) acc[o][j] = 0.f;

    const int HWi = Hi * Wi;
    const float* Xn = X + (size_t)n * CCC * HWi;

    for (int c = 0; c < CCC; c++) {
        __syncthreads();
        // per-channel weights: K2*9 floats into smem
        for (int i = tid; i < K2 * 9; i += 128)
            ws[i] = Wt[((i / 9) * CCC + c) * 9 + (i % 9)];
        // input tile with halo
        const float* Xc = Xn + (size_t)c * HWi;
        for (int i = tid; i < 6 * (TW + 2); i += 128) {
            int r = i / (TW + 2), cc2 = i % (TW + 2);
            int gy = y0 - 1 + r, gx = cc2 - 1;
            float v = 0.f;
            if ((unsigned)gy < (unsigned)Hi && (unsigned)gx < (unsigned)Wi)
                v = Xc[gy * Wi + gx];
            tile[r][cc2] = v;
        }
        __syncthreads();

        float win[3][XPT + 2];
#pragma unroll
        for (int r = 0; r < 3; r++)
#pragma unroll
            for (int j = 0; j < XPT + 2; j++)
                win[r][j] = tile[ty + r][tx * XPT + j];

#pragma unroll
        for (int o = 0; o < K2; o++)
#pragma unroll
            for (int r = 0; r < 3; r++)
#pragma unroll
                for (int dc = 0; dc < 3; dc++) {
                    float w = ws[o * 9 + r * 3 + dc];
#pragma unroll
                    for (int j = 0; j < XPT; j++)
                        acc[o][j] += w * win[r][j + dc];
                }
    }

    const int y = y0 + ty;
#pragma unroll
    for (int o = 0; o < K2; o++) {
        float bv = Bi[o];
        size_t base = (((size_t)n * K2 + o) * Hi + y) * Wi + tx * XPT;
#pragma unroll
        for (int j = 0; j < XPT; j++) Y[base + j] = acc[o][j] + bv;
    }
}

// ---------------------------------------------------------------------------
// kernel_normalizer == per-pixel softmax over K2 channel axis (mc==1).
// Layout [n][K2][HWX]. One thread per pixel; coalesced strided reads.
// ---------------------------------------------------------------------------
template<int K2>
__global__ void softmax_kernel(const float* __restrict__ X, float* __restrict__ Y)
{
    const int p = blockIdx.x * 256 + threadIdx.x;
    const int n = blockIdx.z;
    const float* xp = X + (size_t)n * K2 * HWX + p;
    float v[K2];
    float mx = -1e30f;
#pragma unroll
    for (int j = 0; j < K2; j++) { v[j] = xp[(size_t)j * HWX]; mx = fmaxf(mx, v[j]); }
    float s = 0.f;
#pragma unroll
    for (int j = 0; j < K2; j++) { v[j] = __expf(v[j] - mx); s += v[j]; }
    float inv = 1.f / s;
    float* yp = Y + (size_t)n * K2 * HWX + p;
#pragma unroll
    for (int j = 0; j < K2; j++) yp[(size_t)j * HWX] = v[j] * inv;
}

// ---------------------------------------------------------------------------
// CARAFE scale=1, k=3, fused residual: Y = 2*F - sum_j m[j]*window[j]
// blockDim(32,4); thread handles 4 consecutive x-pixels in one row.
// ---------------------------------------------------------------------------
__global__ void __launch_bounds__(128) carafe_s1_kernel(
    const float* __restrict__ F, const float* __restrict__ M,
    float* __restrict__ Y, int C)
{
    const int n  = blockIdx.z;
    const int y0 = blockIdx.y * 4;
    const int tx = threadIdx.x, ty = threadIdx.y;
    const int tid = ty * 32 + tx;
    __shared__ float tile[6][136];

    const int y  = y0 + ty;
    const int xb = tx * 4;

    // normalized masks for this thread's 4 pixels (loaded once)
    float mk[9][4];
    const float* Mn = M + (size_t)n * 9 * HWX;
#pragma unroll
    for (int j = 0; j < 9; j++) {
        float4 m4 = *(const float4*)&Mn[(size_t)j * HWX + y * WW + xb];
        mk[j][0] = m4.x; mk[j][1] = m4.y; mk[j][2] = m4.z; mk[j][3] = m4.w;
    }

    const float* Fn = F + (size_t)n * C * HWX;
    float* Yn = Y + (size_t)n * C * HWX;

    for (int c = 0; c < C; c++) {
        __syncthreads();
        const float* Fc = Fn + (size_t)c * HWX;
        for (int i = tid; i < 6 * 130; i += 128) {
            int r = i / 130, cc2 = i % 130;
            int gy = y0 - 1 + r, gx = cc2 - 1;
            float v = 0.f;
            if ((unsigned)gy < HH && (unsigned)gx < WW) v = Fc[gy * WW + gx];
            tile[r][cc2] = v;
        }
        __syncthreads();

        float win[3][6];
#pragma unroll
        for (int r = 0; r < 3; r++)
#pragma unroll
            for (int j = 0; j < 6; j++)
                win[r][j] = tile[ty + r][xb + j];

        float out[4];
#pragma unroll
        for (int px = 0; px < 4; px++) out[px] = 2.f * win[1][px + 1];
#pragma unroll
        for (int r = 0; r < 3; r++)
#pragma unroll
            for (int dc = 0; dc < 3; dc++)
#pragma unroll
                for (int px = 0; px < 4; px++)
                    out[px] -= mk[r * 3 + dc][px] * win[r][px + dc];

        *(float4*)&Yn[(size_t)c * HWX + y * WW + xb] =
            make_float4(out[0], out[1], out[2], out[3]);
    }
}

// ---------------------------------------------------------------------------
// CARAFE scale=2, k=5 (nearest-upsampled feature taps).
// F: [n][C][64][64], M: [n][25][128][128] normalized, Y: [n][C][128][128].
// Thread handles 2 output x-pixels that share one 5x5 low-res window.
// Optional fused add of a base tensor (in-place safe: reads only own element).
// ---------------------------------------------------------------------------
template<bool ADD>
__global__ void __launch_bounds__(256) carafe_s2_kernel(
    const float* __restrict__ F, const float* __restrict__ M,
    const float* __restrict__ B, float* __restrict__ Y, int C)
{
    const int n  = blockIdx.z;
    const int x0 = blockIdx.x * 64, y0 = blockIdx.y * 8;
    const int tx = threadIdx.x, ty = threadIdx.y;
    const int tid = ty * 32 + tx;
    const int xo = x0 + tx * 2;
    const int yo = y0 + ty;

    __shared__ float tile[8][36];

    float mk0[25], mk1[25];
    const float* Mn = M + (size_t)n * 25 * HWX;
#pragma unroll
    for (int j = 0; j < 25; j++) {
        float2 m2 = *(const float2*)&Mn[(size_t)j * HWX + yo * WW + xo];
        mk0[j] = m2.x; mk1[j] = m2.y;
    }

    const int ylb = y0 / 2 - 2, xlb = x0 / 2 - 2;
    const int rb  = ty >> 1;
    const float* Fn = F + (size_t)n * C * HW2;

    for (int c = 0; c < C; c++) {
        __syncthreads();
        const float* Fc = Fn + (size_t)c * HW2;
        for (int i = tid; i < 8 * 36; i += 256) {
            int r = i / 36, cc2 = i % 36;
            int gy = ylb + r, gx = xlb + cc2;
            float v = 0.f;
            if ((unsigned)gy < H2 && (unsigned)gx < W2) v = Fc[gy * W2 + gx];
            tile[r][cc2] = v;
        }
        __syncthreads();

        float a0 = 0.f, a1 = 0.f;
#pragma unroll
        for (int ki = 0; ki < 5; ki++)
#pragma unroll
            for (int kj = 0; kj < 5; kj++) {
                float v = tile[rb + ki][tx + kj];
                a0 += v * mk0[ki * 5 + kj];
                a1 += v * mk1[ki * 5 + kj];
            }

        size_t oidx = (((size_t)n * C + c) * HH + yo) * WW + xo;
        if (ADD) {
            float2 b2 = *(const float2*)&B[oidx];
            a0 += b2.x; a1 += b2.y;
        }
        *(float2*)&Y[oidx] = make_float2(a0, a1);
    }
}

// ---------------------------------------------------------------------------
// Orchestration (graph-capturable: kernel launches only)
// ---------------------------------------------------------------------------
extern "C" void kernel_launch(void* const* d_in, const int* in_sizes, int n_in,
                              void* d_out, int out_size)
{
    const float* hr_feat = (const float*)d_in[0];
    const float* lr_feat = (const float*)d_in[1];
    const float* hr_w    = (const float*)d_in[2];
    const float* hr_b    = (const float*)d_in[3];
    const float* lr_w    = (const float*)d_in[4];
    const float* lr_b    = (const float*)d_in[5];
    const float* enc_w   = (const float*)d_in[6];
    const float* enc_b   = (const float*)d_in[7];
    const float* enc2_w  = (const float*)d_in[8];
    const float* enc2_b  = (const float*)d_in[9];
    float* out = (float*)d_out;

    float *p_chf, *p_chf2, *p_clf, *p_mhh, *p_sm9, *p_mlh, *p_sm25, *p_mlll, *p_e2clf;
    cudaGetSymbolAddress((void**)&p_chf,   g_chf);
    cudaGetSymbolAddress((void**)&p_chf2,  g_chf2);
    cudaGetSymbolAddress((void**)&p_clf,   g_clf);
    cudaGetSymbolAddress((void**)&p_mhh,   g_mhh);
    cudaGetSymbolAddress((void**)&p_sm9,   g_sm9);
    cudaGetSymbolAddress((void**)&p_mlh,   g_mlh);
    cudaGetSymbolAddress((void**)&p_sm25,  g_sm25);
    cudaGetSymbolAddress((void**)&p_mlll,  g_mlll);
    cudaGetSymbolAddress((void**)&p_e2clf, g_e2clf);

    const size_t MASK_SZ = (size_t)NB * 25 * HWX;   // 1,638,400
    const size_t FEAT_SZ = (size_t)NB * 256 * HWX;  // 16,777,216
    float* out_mask = out;                          // mask_lr_out
    float* out_hr   = out + MASK_SZ;                // hr_out
    float* out_lr   = out + MASK_SZ + FEAT_SZ;      // lr_out

    dim3 bm(32, 4), bm2(32, 8);

    // chf = conv1x1(hr_feat), clf = conv1x1(lr_feat)
    conv1x1_kernel<<<dim3(HWX/256, 1, NB), 256>>>(hr_feat, hr_w, hr_b, p_chf, HWX);
    conv1x1_kernel<<<dim3(HW2/256, 1, NB), 256>>>(lr_feat, lr_w, lr_b, p_clf, HW2);

    // mask_hr_hr = enc2(chf); mask_hr_init = softmax9
    conv3x3_kernel<9, 4><<<dim3(1, HH/4, NB), bm>>>(p_chf, enc2_w, enc2_b, p_mhh, HH, WW);
    softmax_kernel<9><<<dim3(HWX/256, 1, NB), 256>>>(p_mhh, p_sm9);

    // chf = 2*chf - carafe(chf, mask_hr_init, 3, 1)
    carafe_s1_kernel<<<dim3(1, HH/4, NB), bm>>>(p_chf, p_sm9, p_chf2, CCC);

    // mask_lr_hr = enc(chf'); mask_lr_lr_lr = enc(clf)
    conv3x3_kernel<25, 4><<<dim3(1, HH/4, NB), bm>>>(p_chf2, enc_w, enc_b, p_mlh, HH, WW);
    conv3x3_kernel<25, 2><<<dim3(1, H2/4, NB), bm>>>(p_clf, enc_w, enc_b, p_mlll, H2, W2);

    // mask_lr = mask_lr_hr + carafe(mask_lr_lr_lr, softmax25(mask_lr_hr), 5, 2)
    softmax_kernel<25><<<dim3(HWX/256, 1, NB), 256>>>(p_mlh, p_sm25);
    carafe_s2_kernel<true><<<dim3(WW/64, HH/8, NB), bm2>>>(p_mlll, p_sm25, p_mlh, p_mlh, 25);

    // mask_lr_out = softmax25(mask_lr)  -> output 0 (also reused as operand)
    softmax_kernel<25><<<dim3(HWX/256, 1, NB), 256>>>(p_mlh, out_mask);

    // mask_hr = mask_hr_hr + carafe(enc2(clf), mask_lr_out, 5, 2)
    conv3x3_kernel<9, 2><<<dim3(1, H2/4, NB), bm>>>(p_clf, enc2_w, enc2_b, p_e2clf, H2, W2);
    carafe_s2_kernel<true><<<dim3(WW/64, HH/8, NB), bm2>>>(p_e2clf, out_mask, p_mhh, p_mhh, 9);

    // hr_out = 2*hr_feat - carafe(hr_feat, softmax9(mask_hr), 3, 1)  -> output 1
    softmax_kernel<9><<<dim3(HWX/256, 1, NB), 256>>>(p_mhh, p_sm9);
    carafe_s1_kernel<<<dim3(1, HH/4, NB), bm>>>(hr_feat, p_sm9, out_hr, 256);

    // lr_out = carafe(lr_feat, mask_lr_out, 5, 2)  -> output 2
    carafe_s2_kernel<false><<<dim3(WW/64, HH/8, NB), bm2>>>(lr_feat, out_mask, nullptr, out_lr, 256);
}

// round 12
// speedup vs baseline: 1.0104x; 1.0104x over previous
#include <cuda_runtime.h>

// ---------------------------------------------------------------------------
// Problem constants (fixed shapes from setup_inputs)
// ---------------------------------------------------------------------------
#define NB   4
#define CIN  256          // CH == CL == 256
#define CCC  64           // compressed channels
#define HH   128
#define WW   128
#define HWX  (HH*WW)      // 16384
#define H2   64
#define W2   64
#define HW2  (H2*W2)      // 4096

// ---------------------------------------------------------------------------
// Device-global scratch (no cudaMalloc allowed)
// ---------------------------------------------------------------------------
__device__ float g_chf  [NB*CCC*HWX];   // 16 MB
__device__ float g_chf2 [NB*CCC*HWX];   // 16 MB
__device__ float g_clf  [NB*CCC*HW2];   // 4 MB
__device__ float g_mhh  [NB*9 *HWX];    // mask_hr_hr -> mask_hr (in-place add)
__device__ float g_sm9  [NB*9 *HWX];    // softmax scratch (k=3 masks)
__device__ float g_mlh  [NB*25*HWX];    // mask_lr_hr -> mask_lr (in-place add)
__device__ float g_sm25 [NB*25*HWX];    // softmax(mask_lr_hr)
__device__ float g_mlll [NB*25*HW2];    // enc(clf)
__device__ float g_e2clf[NB*9 *HW2];    // enc2(clf)

// ---------------------------------------------------------------------------
// conv1x1 as SGEMM: Y[n][oc][p] = b[oc] + sum_c W[oc][c] * X[n][c][p]
// M=64, K=256; BN=256 pixels, BK=16; thread tile 8x8 (8 oc x 8 pixels)
// ---------------------------------------------------------------------------
__global__ void __launch_bounds__(256) conv1x1_kernel(
    const float* __restrict__ X, const float* __restrict__ Wt,
    const float* __restrict__ Bi, float* __restrict__ Y, int P)
{
    __shared__ float Ws[16][64];
    __shared__ float Xs[16][256];
    const int n  = blockIdx.z;
    const int p0 = blockIdx.x * 256;
    const int tid = threadIdx.x;
    const int tx = tid & 31;   // pixel group (8 px each)
    const int ty = tid >> 5;   // oc group (8 oc each)
    const float* Xn = X + (size_t)n * CIN * P;

    float acc[8][8];
#pragma unroll
    for (int i = 0; i < 8; i++)
#pragma unroll
        for (int j = 0; j < 8; j++) acc[i][j] = 0.f;

    for (int k0 = 0; k0 < CIN; k0 += 16) {
        // load 16x64 weight tile
#pragma unroll
        for (int i = 0; i < 4; i++) {
            int idx = i * 256 + tid;
            int kk = idx >> 6, mm = idx & 63;
            Ws[kk][mm] = Wt[mm * CIN + k0 + kk];
        }
        // load 16x256 activation tile (float4, coalesced)
#pragma unroll
        for (int i = 0; i < 4; i++) {
            int idx = i * 256 + tid;
            int kk = idx >> 6;
            int pp = (idx & 63) << 2;
            *(float4*)&Xs[kk][pp] =
                *(const float4*)&Xn[(size_t)(k0 + kk) * P + p0 + pp];
        }
        __syncthreads();
#pragma unroll
        for (int k = 0; k < 16; k++) {
            float rw[8], rx[8];
            *(float4*)&rw[0] = *(float4*)&Ws[k][ty * 8];
            *(float4*)&rw[4] = *(float4*)&Ws[k][ty * 8 + 4];
            *(float4*)&rx[0] = *(float4*)&Xs[k][tx * 8];
            *(float4*)&rx[4] = *(float4*)&Xs[k][tx * 8 + 4];
#pragma unroll
            for (int i = 0; i < 8; i++)
#pragma unroll
                for (int j = 0; j < 8; j++)
                    acc[i][j] += rw[i] * rx[j];
        }
        __syncthreads();
    }

#pragma unroll
    for (int i = 0; i < 8; i++) {
        int oc = ty * 8 + i;
        float bv = Bi[oc];
        size_t base = ((size_t)n * CCC + oc) * P + p0 + tx * 8;
        float4 v0 = make_float4(acc[i][0]+bv, acc[i][1]+bv, acc[i][2]+bv, acc[i][3]+bv);
        float4 v1 = make_float4(acc[i][4]+bv, acc[i][5]+bv, acc[i][6]+bv, acc[i][7]+bv);
        *(float4*)&Y[base]     = v0;
        *(float4*)&Y[base + 4] = v1;
    }
}

// ---------------------------------------------------------------------------
// conv3x3, pad=1, Cin=64, Cout=K2 (9 or 25).
// blockDim(32,4); each thread produces XPT consecutive x-pixels in one row.
// tile = full row width (32*XPT == Wi) x 4 rows, +1 halo each side.
// ---------------------------------------------------------------------------
template<int K2, int XPT>
__global__ void __launch_bounds__(128) conv3x3_kernel(
    const float* __restrict__ X, const float* __restrict__ Wt,
    const float* __restrict__ Bi, float* __restrict__ Y,
    int Hi, int Wi)
{
    const int TW = 32 * XPT;          // == Wi
    const int n  = blockIdx.z;
    const int y0 = blockIdx.y * 4;
    const int tx = threadIdx.x, ty = threadIdx.y;
    const int tid = ty * 32 + tx;

    __shared__ float ws[K2 * 9];
    __shared__ float tile[6][32 * XPT + 8];

    float acc[K2][XPT];
#pragma unroll
    for (int o = 0; o < K2; o++)
#pragma unroll
        for (int j = 0; j < XPT; j++) acc[o][j] = 0.f;

    const int HWi = Hi * Wi;
    const float* Xn = X + (size_t)n * CCC * HWi;

    for (int c = 0; c < CCC; c++) {
        __syncthreads();
        // per-channel weights: K2*9 floats into smem
        for (int i = tid; i < K2 * 9; i += 128)
            ws[i] = Wt[((i / 9) * CCC + c) * 9 + (i % 9)];
        // input tile with halo
        const float* Xc = Xn + (size_t)c * HWi;
        for (int i = tid; i < 6 * (TW + 2); i += 128) {
            int r = i / (TW + 2), cc2 = i % (TW + 2);
            int gy = y0 - 1 + r, gx = cc2 - 1;
            float v = 0.f;
            if ((unsigned)gy < (unsigned)Hi && (unsigned)gx < (unsigned)Wi)
                v = Xc[gy * Wi + gx];
            tile[r][cc2] = v;
        }
        __syncthreads();

        float win[3][XPT + 2];
#pragma unroll
        for (int r = 0; r < 3; r++)
#pragma unroll
            for (int j = 0; j < XPT + 2; j++)
                win[r][j] = tile[ty + r][tx * XPT + j];

#pragma unroll
        for (int o = 0; o < K2; o++)
#pragma unroll
            for (int r = 0; r < 3; r++)
#pragma unroll
                for (int dc = 0; dc < 3; dc++) {
                    float w = ws[o * 9 + r * 3 + dc];
#pragma unroll
                    for (int j = 0; j < XPT; j++)
                        acc[o][j] += w * win[r][j + dc];
                }
    }

    const int y = y0 + ty;
#pragma unroll
    for (int o = 0; o < K2; o++) {
        float bv = Bi[o];
        size_t base = (((size_t)n * K2 + o) * Hi + y) * Wi + tx * XPT;
#pragma unroll
        for (int j = 0; j < XPT; j++) Y[base + j] = acc[o][j] + bv;
    }
}

// ---------------------------------------------------------------------------
// kernel_normalizer == per-pixel softmax over K2 channel axis (mc==1).
// Layout [n][K2][HWX]. One thread per pixel; coalesced strided reads.
// ---------------------------------------------------------------------------
template<int K2>
__global__ void softmax_kernel(const float* __restrict__ X, float* __restrict__ Y)
{
    const int p = blockIdx.x * 256 + threadIdx.x;
    const int n = blockIdx.z;
    const float* xp = X + (size_t)n * K2 * HWX + p;
    float v[K2];
    float mx = -1e30f;
#pragma unroll
    for (int j = 0; j < K2; j++) { v[j] = xp[(size_t)j * HWX]; mx = fmaxf(mx, v[j]); }
    float s = 0.f;
#pragma unroll
    for (int j = 0; j < K2; j++) { v[j] = __expf(v[j] - mx); s += v[j]; }
    float inv = 1.f / s;
    float* yp = Y + (size_t)n * K2 * HWX + p;
#pragma unroll
    for (int j = 0; j < K2; j++) yp[(size_t)j * HWX] = v[j] * inv;
}

// ---------------------------------------------------------------------------
// CARAFE scale=1, k=3, fused residual: Y = 2*F - sum_j m[j]*window[j]
// blockDim(32,4); thread handles 4 consecutive x-pixels in one row.
// ---------------------------------------------------------------------------
__global__ void __launch_bounds__(128) carafe_s1_kernel(
    const float* __restrict__ F, const float* __restrict__ M,
    float* __restrict__ Y, int C)
{
    const int n  = blockIdx.z;
    const int y0 = blockIdx.y * 4;
    const int tx = threadIdx.x, ty = threadIdx.y;
    const int tid = ty * 32 + tx;
    __shared__ float tile[6][136];

    const int y  = y0 + ty;
    const int xb = tx * 4;

    // normalized masks for this thread's 4 pixels (loaded once)
    float mk[9][4];
    const float* Mn = M + (size_t)n * 9 * HWX;
#pragma unroll
    for (int j = 0; j < 9; j++) {
        float4 m4 = *(const float4*)&Mn[(size_t)j * HWX + y * WW + xb];
        mk[j][0] = m4.x; mk[j][1] = m4.y; mk[j][2] = m4.z; mk[j][3] = m4.w;
    }

    const float* Fn = F + (size_t)n * C * HWX;
    float* Yn = Y + (size_t)n * C * HWX;

    for (int c = 0; c < C; c++) {
        __syncthreads();
        const float* Fc = Fn + (size_t)c * HWX;
        for (int i = tid; i < 6 * 130; i += 128) {
            int r = i / 130, cc2 = i % 130;
            int gy = y0 - 1 + r, gx = cc2 - 1;
            float v = 0.f;
            if ((unsigned)gy < HH && (unsigned)gx < WW) v = Fc[gy * WW + gx];
            tile[r][cc2] = v;
        }
        __syncthreads();

        float win[3][6];
#pragma unroll
        for (int r = 0; r < 3; r++)
#pragma unroll
            for (int j = 0; j < 6; j++)
                win[r][j] = tile[ty + r][xb + j];

        float out[4];
#pragma unroll
        for (int px = 0; px < 4; px++) out[px] = 2.f * win[1][px + 1];
#pragma unroll
        for (int r = 0; r < 3; r++)
#pragma unroll
            for (int dc = 0; dc < 3; dc++)
#pragma unroll
                for (int px = 0; px < 4; px++)
                    out[px] -= mk[r * 3 + dc][px] * win[r][px + dc];

        *(float4*)&Yn[(size_t)c * HWX + y * WW + xb] =
            make_float4(out[0], out[1], out[2], out[3]);
    }
}

// ---------------------------------------------------------------------------
// CARAFE scale=2, k=5 (nearest-upsampled feature taps).
// F: [n][C][64][64], M: [n][25][128][128] normalized, Y: [n][C][128][128].
// Thread handles 2 output x-pixels that share one 5x5 low-res window.
// Optional fused add of a base tensor (in-place safe: reads only own element).
// ---------------------------------------------------------------------------
template<bool ADD>
__global__ void __launch_bounds__(256) carafe_s2_kernel(
    const float* __restrict__ F, const float* __restrict__ M,
    const float* __restrict__ B, float* __restrict__ Y, int C)
{
    const int n  = blockIdx.z;
    const int x0 = blockIdx.x * 64, y0 = blockIdx.y * 8;
    const int tx = threadIdx.x, ty = threadIdx.y;
    const int tid = ty * 32 + tx;
    const int xo = x0 + tx * 2;
    const int yo = y0 + ty;

    __shared__ float tile[8][36];

    float mk0[25], mk1[25];
    const float* Mn = M + (size_t)n * 25 * HWX;
#pragma unroll
    for (int j = 0; j < 25; j++) {
        float2 m2 = *(const float2*)&Mn[(size_t)j * HWX + yo * WW + xo];
        mk0[j] = m2.x; mk1[j] = m2.y;
    }

    const int ylb = y0 / 2 - 2, xlb = x0 / 2 - 2;
    const int rb  = ty >> 1;
    const float* Fn = F + (size_t)n * C * HW2;

    for (int c = 0; c < C; c++) {
        __syncthreads();
        const float* Fc = Fn + (size_t)c * HW2;
        for (int i = tid; i < 8 * 36; i += 256) {
            int r = i / 36, cc2 = i % 36;
            int gy = ylb + r, gx = xlb + cc2;
            float v = 0.f;
            if ((unsigned)gy < H2 && (unsigned)gx < W2) v = Fc[gy * W2 + gx];
            tile[r][cc2] = v;
        }
        __syncthreads();

        float a0 = 0.f, a1 = 0.f;
#pragma unroll
        for (int ki = 0; ki < 5; ki++)
#pragma unroll
            for (int kj = 0; kj < 5; kj++) {
                float v = tile[rb + ki][tx + kj];
                a0 += v * mk0[ki * 5 + kj];
                a1 += v * mk1[ki * 5 + kj];
            }

        size_t oidx = (((size_t)n * C + c) * HH + yo) * WW + xo;
        if (ADD) {
            float2 b2 = *(const float2*)&B[oidx];
            a0 += b2.x; a1 += b2.y;
        }
        *(float2*)&Y[oidx] = make_float2(a0, a1);
    }
}

// ---------------------------------------------------------------------------
// Orchestration (graph-capturable: kernel launches only)
// ---------------------------------------------------------------------------
extern "C" void kernel_launch(void* const* d_in, const int* in_sizes, int n_in,
                              void* d_out, int out_size)
{
    const float* hr_feat = (const float*)d_in[0];
    const float* lr_feat = (const float*)d_in[1];
    const float* hr_w    = (const float*)d_in[2];
    const float* hr_b    = (const float*)d_in[3];
    const float* lr_w    = (const float*)d_in[4];
    const float* lr_b    = (const float*)d_in[5];
    const float* enc_w   = (const float*)d_in[6];
    const float* enc_b   = (const float*)d_in[7];
    const float* enc2_w  = (const float*)d_in[8];
    const float* enc2_b  = (const float*)d_in[9];
    float* out = (float*)d_out;

    float *p_chf, *p_chf2, *p_clf, *p_mhh, *p_sm9, *p_mlh, *p_sm25, *p_mlll, *p_e2clf;
    cudaGetSymbolAddress((void**)&p_chf,   g_chf);
    cudaGetSymbolAddress((void**)&p_chf2,  g_chf2);
    cudaGetSymbolAddress((void**)&p_clf,   g_clf);
    cudaGetSymbolAddress((void**)&p_mhh,   g_mhh);
    cudaGetSymbolAddress((void**)&p_sm9,   g_sm9);
    cudaGetSymbolAddress((void**)&p_mlh,   g_mlh);
    cudaGetSymbolAddress((void**)&p_sm25,  g_sm25);
    cudaGetSymbolAddress((void**)&p_mlll,  g_mlll);
    cudaGetSymbolAddress((void**)&p_e2clf, g_e2clf);

    const size_t MASK_SZ = (size_t)NB * 25 * HWX;   // 1,638,400
    const size_t FEAT_SZ = (size_t)NB * 256 * HWX;  // 16,777,216
    float* out_mask = out;                          // mask_lr_out
    float* out_hr   = out + MASK_SZ;                // hr_out
    float* out_lr   = out + MASK_SZ + FEAT_SZ;      // lr_out

    dim3 bm(32, 4), bm2(32, 8);

    // chf = conv1x1(hr_feat), clf = conv1x1(lr_feat)
    conv1x1_kernel<<<dim3(HWX/256, 1, NB), 256>>>(hr_feat, hr_w, hr_b, p_chf, HWX);
    conv1x1_kernel<<<dim3(HW2/256, 1, NB), 256>>>(lr_feat, lr_w, lr_b, p_clf, HW2);

    // mask_hr_hr = enc2(chf); mask_hr_init = softmax9
    conv3x3_kernel<9, 4><<<dim3(1, HH/4, NB), bm>>>(p_chf, enc2_w, enc2_b, p_mhh, HH, WW);
    softmax_kernel<9><<<dim3(HWX/256, 1, NB), 256>>>(p_mhh, p_sm9);

    // chf = 2*chf - carafe(chf, mask_hr_init, 3, 1)
    carafe_s1_kernel<<<dim3(1, HH/4, NB), bm>>>(p_chf, p_sm9, p_chf2, CCC);

    // mask_lr_hr = enc(chf'); mask_lr_lr_lr = enc(clf)
    conv3x3_kernel<25, 4><<<dim3(1, HH/4, NB), bm>>>(p_chf2, enc_w, enc_b, p_mlh, HH, WW);
    conv3x3_kernel<25, 2><<<dim3(1, H2/4, NB), bm>>>(p_clf, enc_w, enc_b, p_mlll, H2, W2);

    // mask_lr = mask_lr_hr + carafe(mask_lr_lr_lr, softmax25(mask_lr_hr), 5, 2)
    softmax_kernel<25><<<dim3(HWX/256, 1, NB), 256>>>(p_mlh, p_sm25);
    carafe_s2_kernel<true><<<dim3(WW/64, HH/8, NB), bm2>>>(p_mlll, p_sm25, p_mlh, p_mlh, 25);

    // mask_lr_out = softmax25(mask_lr)  -> output 0 (also reused as operand)
    softmax_kernel<25><<<dim3(HWX/256, 1, NB), 256>>>(p_mlh, out_mask);

    // mask_hr = mask_hr_hr + carafe(enc2(clf), mask_lr_out, 5, 2)
    conv3x3_kernel<9, 2><<<dim3(1, H2/4, NB), bm>>>(p_clf, enc2_w, enc2_b, p_e2clf, H2, W2);
    carafe_s2_kernel<true><<<dim3(WW/64, HH/8, NB), bm2>>>(p_e2clf, out_mask, p_mhh, p_mhh, 9);

    // hr_out = 2*hr_feat - carafe(hr_feat, softmax9(mask_hr), 3, 1)  -> output 1
    softmax_kernel<9><<<dim3(HWX/256, 1, NB), 256>>>(p_mhh, p_sm9);
    carafe_s1_kernel<<<dim3(1, HH/4, NB), bm>>>(hr_feat, p_sm9, out_hr, 256);

    // lr_out = carafe(lr_feat, mask_lr_out, 5, 2)  -> output 2
    carafe_s2_kernel<false><<<dim3(WW/64, HH/8, NB), bm2>>>(lr_feat, out_mask, nullptr, out_lr, 256);
}

// round 13
// speedup vs baseline: 2.0362x; 2.0152x over previous
#include <cuda_runtime.h>

// ---------------------------------------------------------------------------
// Problem constants (fixed shapes from setup_inputs)
// ---------------------------------------------------------------------------
#define NB   4
#define CIN  256          // CH == CL == 256
#define CCC  64           // compressed channels
#define HH   128
#define WW   128
#define HWX  (HH*WW)      // 16384
#define H2   64
#define W2   64
#define HW2  (H2*W2)      // 4096

// ---------------------------------------------------------------------------
// Device-global scratch (no cudaMalloc allowed)
// ---------------------------------------------------------------------------
__device__ float g_chf  [NB*CCC*HWX];   // 16 MB
__device__ float g_chf2 [NB*CCC*HWX];   // 16 MB
__device__ float g_clf  [NB*CCC*HW2];   // 4 MB
__device__ float g_mhh  [NB*9 *HWX];    // mask_hr_hr -> mask_hr (in-place add)
__device__ float g_mlh  [NB*25*HWX];    // mask_lr_hr -> mask_lr (in-place add)
__device__ float g_sm25 [NB*25*HWX];    // softmax(mask_lr_hr)
__device__ float g_mlll [NB*25*HW2];    // enc(clf)
__device__ float g_e2clf[NB*9 *HW2];    // enc2(clf)

// ---------------------------------------------------------------------------
// conv1x1 as SGEMM: Y[n][oc][p] = b[oc] + sum_c W[oc][c] * X[n][c][p]
// M=64, K=256; BN=256 pixels, BK=16; thread tile 8x8 (8 oc x 8 pixels)
// ---------------------------------------------------------------------------
__global__ void __launch_bounds__(256) conv1x1_kernel(
    const float* __restrict__ X, const float* __restrict__ Wt,
    const float* __restrict__ Bi, float* __restrict__ Y, int P)
{
    __shared__ float Ws[16][64];
    __shared__ float Xs[16][256];
    const int n  = blockIdx.z;
    const int p0 = blockIdx.x * 256;
    const int tid = threadIdx.x;
    const int tx = tid & 31;   // pixel group (8 px each)
    const int ty = tid >> 5;   // oc group (8 oc each)
    const float* Xn = X + (size_t)n * CIN * P;

    float acc[8][8];
#pragma unroll
    for (int i = 0; i < 8; i++)
#pragma unroll
        for (int j = 0; j < 8; j++) acc[i][j] = 0.f;

    for (int k0 = 0; k0 < CIN; k0 += 16) {
#pragma unroll
        for (int i = 0; i < 4; i++) {
            int idx = i * 256 + tid;
            int kk = idx >> 6, mm = idx & 63;
            Ws[kk][mm] = Wt[mm * CIN + k0 + kk];
        }
#pragma unroll
        for (int i = 0; i < 4; i++) {
            int idx = i * 256 + tid;
            int kk = idx >> 6;
            int pp = (idx & 63) << 2;
            *(float4*)&Xs[kk][pp] =
                *(const float4*)&Xn[(size_t)(k0 + kk) * P + p0 + pp];
        }
        __syncthreads();
#pragma unroll
        for (int k = 0; k < 16; k++) {
            float rw[8], rx[8];
            *(float4*)&rw[0] = *(float4*)&Ws[k][ty * 8];
            *(float4*)&rw[4] = *(float4*)&Ws[k][ty * 8 + 4];
            *(float4*)&rx[0] = *(float4*)&Xs[k][tx * 8];
            *(float4*)&rx[4] = *(float4*)&Xs[k][tx * 8 + 4];
#pragma unroll
            for (int i = 0; i < 8; i++)
#pragma unroll
                for (int j = 0; j < 8; j++)
                    acc[i][j] += rw[i] * rx[j];
        }
        __syncthreads();
    }

#pragma unroll
    for (int i = 0; i < 8; i++) {
        int oc = ty * 8 + i;
        float bv = Bi[oc];
        size_t base = ((size_t)n * CCC + oc) * P + p0 + tx * 8;
        float4 v0 = make_float4(acc[i][0]+bv, acc[i][1]+bv, acc[i][2]+bv, acc[i][3]+bv);
        float4 v1 = make_float4(acc[i][4]+bv, acc[i][5]+bv, acc[i][6]+bv, acc[i][7]+bv);
        *(float4*)&Y[base]     = v0;
        *(float4*)&Y[base + 4] = v1;
    }
}

// ---------------------------------------------------------------------------
// conv3x3, pad=1, Cin=64. Output channels split across blocks in chunks of
// K2C (blockIdx.x). All chunk weights preloaded to smem once; input tile is
// double-buffered -> ONE __syncthreads per channel.
// blockDim(32,4); thread produces XPT consecutive x-pixels in one row.
// ---------------------------------------------------------------------------
template<int K2C, int K2, int XPT>
__global__ void __launch_bounds__(128) conv3x3_kernel(
    const float* __restrict__ X, const float* __restrict__ Wt,
    const float* __restrict__ Bi, float* __restrict__ Y,
    int Hi, int Wi)
{
    const int TW = 32 * XPT;          // == Wi
    const int n   = blockIdx.z;
    const int oc0 = blockIdx.x * K2C;
    const int y0  = blockIdx.y * 4;
    const int tx = threadIdx.x, ty = threadIdx.y;
    const int tid = ty * 32 + tx;

    __shared__ float ws[CCC * K2C * 9];
    __shared__ float tile[2][6][32 * XPT + 8];

    // preload all weights for this output-channel chunk (once)
    for (int i = tid; i < CCC * K2C * 9; i += 128) {
        int c = i / (K2C * 9);
        int r = i % (K2C * 9);
        int o = r / 9, k = r % 9;
        ws[i] = Wt[((oc0 + o) * CCC + c) * 9 + k];
    }

    float acc[K2C][XPT];
#pragma unroll
    for (int o = 0; o < K2C; o++)
#pragma unroll
        for (int j = 0; j < XPT; j++) acc[o][j] = 0.f;

    const int HWi = Hi * Wi;
    const float* Xn = X + (size_t)n * CCC * HWi;

#pragma unroll 1
    for (int c = 0; c < CCC; c++) {
        const float* Xc = Xn + (size_t)c * HWi;
        float (*tb)[32 * XPT + 8] = tile[c & 1];
        for (int i = tid; i < 6 * (TW + 2); i += 128) {
            int r = i / (TW + 2), cc2 = i % (TW + 2);
            int gy = y0 - 1 + r, gx = cc2 - 1;
            float v = 0.f;
            if ((unsigned)gy < (unsigned)Hi && (unsigned)gx < (unsigned)Wi)
                v = Xc[gy * Wi + gx];
            tb[r][cc2] = v;
        }
        __syncthreads();   // covers ws preload on first iteration too

        float win[3][XPT + 2];
#pragma unroll
        for (int r = 0; r < 3; r++)
#pragma unroll
            for (int j = 0; j < XPT + 2; j++)
                win[r][j] = tb[ty + r][tx * XPT + j];

        const float* wc = &ws[c * K2C * 9];
#pragma unroll
        for (int o = 0; o < K2C; o++)
#pragma unroll
            for (int r = 0; r < 3; r++)
#pragma unroll
                for (int dc = 0; dc < 3; dc++) {
                    float w = wc[o * 9 + r * 3 + dc];
#pragma unroll
                    for (int j = 0; j < XPT; j++)
                        acc[o][j] += w * win[r][j + dc];
                }
    }

    const int y = y0 + ty;
#pragma unroll
    for (int o = 0; o < K2C; o++) {
        float bv = Bi[oc0 + o];
        size_t base = (((size_t)n * K2 + oc0 + o) * Hi + y) * Wi + tx * XPT;
#pragma unroll
        for (int j = 0; j < XPT; j++) Y[base + j] = acc[o][j] + bv;
    }
}

// ---------------------------------------------------------------------------
// per-pixel softmax over K2 channel axis. Layout [n][K2][HWX].
// ---------------------------------------------------------------------------
template<int K2>
__global__ void softmax_kernel(const float* __restrict__ X, float* __restrict__ Y)
{
    const int p = blockIdx.x * 256 + threadIdx.x;
    const int n = blockIdx.z;
    const float* xp = X + (size_t)n * K2 * HWX + p;
    float v[K2];
    float mx = -1e30f;
#pragma unroll
    for (int j = 0; j < K2; j++) { v[j] = xp[(size_t)j * HWX]; mx = fmaxf(mx, v[j]); }
    float s = 0.f;
#pragma unroll
    for (int j = 0; j < K2; j++) { v[j] = __expf(v[j] - mx); s += v[j]; }
    float inv = 1.f / s;
    float* yp = Y + (size_t)n * K2 * HWX + p;
#pragma unroll
    for (int j = 0; j < K2; j++) yp[(size_t)j * HWX] = v[j] * inv;
}

// ---------------------------------------------------------------------------
// CARAFE scale=1, k=3, fused residual + INLINE softmax over the 9 raw mask
// logits: Y = 2*F - sum_j softmax(m)[j]*window[j].
// Channel-chunked: blockIdx.x selects 16 channels. Double-buffered tile.
// ---------------------------------------------------------------------------
__global__ void __launch_bounds__(128) carafe_s1_kernel(
    const float* __restrict__ F, const float* __restrict__ M,
    float* __restrict__ Y, int C)
{
    const int n  = blockIdx.z;
    const int y0 = blockIdx.y * 4;
    const int c0 = blockIdx.x * 16;
    const int tx = threadIdx.x, ty = threadIdx.y;
    const int tid = ty * 32 + tx;
    __shared__ float tile[2][6][136];

    const int y  = y0 + ty;
    const int xb = tx * 4;

    // raw mask logits for this thread's 4 pixels -> softmax in registers
    float mk[9][4];
    const float* Mn = M + (size_t)n * 9 * HWX;
#pragma unroll
    for (int j = 0; j < 9; j++) {
        float4 m4 = *(const float4*)&Mn[(size_t)j * HWX + y * WW + xb];
        mk[j][0] = m4.x; mk[j][1] = m4.y; mk[j][2] = m4.z; mk[j][3] = m4.w;
    }
#pragma unroll
    for (int px = 0; px < 4; px++) {
        float mx = mk[0][px];
#pragma unroll
        for (int j = 1; j < 9; j++) mx = fmaxf(mx, mk[j][px]);
        float s = 0.f;
#pragma unroll
        for (int j = 0; j < 9; j++) { mk[j][px] = __expf(mk[j][px] - mx); s += mk[j][px]; }
        float inv = 1.f / s;
#pragma unroll
        for (int j = 0; j < 9; j++) mk[j][px] *= inv;
    }

    const float* Fn = F + (size_t)n * C * HWX;
    float* Yn = Y + (size_t)n * C * HWX;

#pragma unroll 1
    for (int cc = 0; cc < 16; cc++) {
        const int c = c0 + cc;
        const float* Fc = Fn + (size_t)c * HWX;
        float (*tb)[136] = tile[cc & 1];
        for (int i = tid; i < 6 * 130; i += 128) {
            int r = i / 130, cc2 = i % 130;
            int gy = y0 - 1 + r, gx = cc2 - 1;
            float v = 0.f;
            if ((unsigned)gy < HH && (unsigned)gx < WW) v = Fc[gy * WW + gx];
            tb[r][cc2] = v;
        }
        __syncthreads();

        float win[3][6];
#pragma unroll
        for (int r = 0; r < 3; r++)
#pragma unroll
            for (int j = 0; j < 6; j++)
                win[r][j] = tb[ty + r][xb + j];

        float out[4];
#pragma unroll
        for (int px = 0; px < 4; px++) out[px] = 2.f * win[1][px + 1];
#pragma unroll
        for (int r = 0; r < 3; r++)
#pragma unroll
            for (int dc = 0; dc < 3; dc++)
#pragma unroll
                for (int px = 0; px < 4; px++)
                    out[px] -= mk[r * 3 + dc][px] * win[r][px + dc];

        *(float4*)&Yn[(size_t)c * HWX + y * WW + xb] =
            make_float4(out[0], out[1], out[2], out[3]);
    }
}

// ---------------------------------------------------------------------------
// CARAFE scale=2, k=5. F:[n][C][64][64], M normalized:[n][25][128][128].
// Channel-chunked (CC per block) + double-buffered tile.
// blockIdx.x encodes (x-tile in bit0, channel chunk above).
// ---------------------------------------------------------------------------
template<bool ADD, int CC>
__global__ void __launch_bounds__(256) carafe_s2_kernel(
    const float* __restrict__ F, const float* __restrict__ M,
    const float* __restrict__ B, float* __restrict__ Y, int C)
{
    const int n  = blockIdx.z;
    const int xt = blockIdx.x & 1;
    const int c0 = (blockIdx.x >> 1) * CC;
    const int x0 = xt * 64, y0 = blockIdx.y * 8;
    const int tx = threadIdx.x, ty = threadIdx.y;
    const int tid = ty * 32 + tx;
    const int xo = x0 + tx * 2;
    const int yo = y0 + ty;

    __shared__ float tile[2][8][36];

    float mk0[25], mk1[25];
    const float* Mn = M + (size_t)n * 25 * HWX;
#pragma unroll
    for (int j = 0; j < 25; j++) {
        float2 m2 = *(const float2*)&Mn[(size_t)j * HWX + yo * WW + xo];
        mk0[j] = m2.x; mk1[j] = m2.y;
    }

    const int ylb = y0 / 2 - 2, xlb = x0 / 2 - 2;
    const int rb  = ty >> 1;
    const float* Fn = F + (size_t)n * C * HW2;
    const int cend = (c0 + CC < C) ? c0 + CC : C;

#pragma unroll 1
    for (int c = c0; c < cend; c++) {
        const float* Fc = Fn + (size_t)c * HW2;
        float (*tb)[36] = tile[c & 1];
        for (int i = tid; i < 8 * 36; i += 256) {
            int r = i / 36, cc2 = i % 36;
            int gy = ylb + r, gx = xlb + cc2;
            float v = 0.f;
            if ((unsigned)gy < H2 && (unsigned)gx < W2) v = Fc[gy * W2 + gx];
            tb[r][cc2] = v;
        }
        __syncthreads();

        float a0 = 0.f, a1 = 0.f;
#pragma unroll
        for (int ki = 0; ki < 5; ki++)
#pragma unroll
            for (int kj = 0; kj < 5; kj++) {
                float v = tb[rb + ki][tx + kj];
                a0 += v * mk0[ki * 5 + kj];
                a1 += v * mk1[ki * 5 + kj];
            }

        size_t oidx = (((size_t)n * C + c) * HH + yo) * WW + xo;
        if (ADD) {
            float2 b2 = *(const float2*)&B[oidx];
            a0 += b2.x; a1 += b2.y;
        }
        *(float2*)&Y[oidx] = make_float2(a0, a1);
    }
}

// ---------------------------------------------------------------------------
// Orchestration (graph-capturable: kernel launches only)
// ---------------------------------------------------------------------------
extern "C" void kernel_launch(void* const* d_in, const int* in_sizes, int n_in,
                              void* d_out, int out_size)
{
    const float* hr_feat = (const float*)d_in[0];
    const float* lr_feat = (const float*)d_in[1];
    const float* hr_w    = (const float*)d_in[2];
    const float* hr_b    = (const float*)d_in[3];
    const float* lr_w    = (const float*)d_in[4];
    const float* lr_b    = (const float*)d_in[5];
    const float* enc_w   = (const float*)d_in[6];
    const float* enc_b   = (const float*)d_in[7];
    const float* enc2_w  = (const float*)d_in[8];
    const float* enc2_b  = (const float*)d_in[9];
    float* out = (float*)d_out;

    float *p_chf, *p_chf2, *p_clf, *p_mhh, *p_mlh, *p_sm25, *p_mlll, *p_e2clf;
    cudaGetSymbolAddress((void**)&p_chf,   g_chf);
    cudaGetSymbolAddress((void**)&p_chf2,  g_chf2);
    cudaGetSymbolAddress((void**)&p_clf,   g_clf);
    cudaGetSymbolAddress((void**)&p_mhh,   g_mhh);
    cudaGetSymbolAddress((void**)&p_mlh,   g_mlh);
    cudaGetSymbolAddress((void**)&p_sm25,  g_sm25);
    cudaGetSymbolAddress((void**)&p_mlll,  g_mlll);
    cudaGetSymbolAddress((void**)&p_e2clf, g_e2clf);

    const size_t MASK_SZ = (size_t)NB * 25 * HWX;
    const size_t FEAT_SZ = (size_t)NB * 256 * HWX;
    float* out_mask = out;                          // mask_lr_out
    float* out_hr   = out + MASK_SZ;                // hr_out
    float* out_lr   = out + MASK_SZ + FEAT_SZ;      // lr_out

    dim3 bm(32, 4), bm2(32, 8);

    // chf = conv1x1(hr_feat), clf = conv1x1(lr_feat)
    conv1x1_kernel<<<dim3(HWX/256, 1, NB), 256>>>(hr_feat, hr_w, hr_b, p_chf, HWX);
    conv1x1_kernel<<<dim3(HW2/256, 1, NB), 256>>>(lr_feat, lr_w, lr_b, p_clf, HW2);

    // mask_hr_hr = enc2(chf)
    conv3x3_kernel<3, 9, 4><<<dim3(3, HH/4, NB), bm>>>(p_chf, enc2_w, enc2_b, p_mhh, HH, WW);

    // chf = 2*chf - carafe(chf, softmax9(mask_hr_hr), 3, 1)   (softmax inlined)
    carafe_s1_kernel<<<dim3(CCC/16, HH/4, NB), bm>>>(p_chf, p_mhh, p_chf2, CCC);

    // mask_lr_hr = enc(chf'); mask_lr_lr_lr = enc(clf)
    conv3x3_kernel<5, 25, 4><<<dim3(5, HH/4, NB), bm>>>(p_chf2, enc_w, enc_b, p_mlh, HH, WW);
    conv3x3_kernel<5, 25, 2><<<dim3(5, H2/4, NB), bm>>>(p_clf, enc_w, enc_b, p_mlll, H2, W2);

    // mask_lr = mask_lr_hr + carafe(mask_lr_lr_lr, softmax25(mask_lr_hr), 5, 2)
    softmax_kernel<25><<<dim3(HWX/256, 1, NB), 256>>>(p_mlh, p_sm25);
    carafe_s2_kernel<true, 8><<<dim3(2 * 4, HH/8, NB), bm2>>>(p_mlll, p_sm25, p_mlh, p_mlh, 25);

    // mask_lr_out = softmax25(mask_lr) -> output 0 (also operand of last carafes)
    softmax_kernel<25><<<dim3(HWX/256, 1, NB), 256>>>(p_mlh, out_mask);

    // mask_hr = mask_hr_hr + carafe(enc2(clf), mask_lr_out, 5, 2)
    conv3x3_kernel<3, 9, 2><<<dim3(3, H2/4, NB), bm>>>(p_clf, enc2_w, enc2_b, p_e2clf, H2, W2);
    carafe_s2_kernel<true, 8><<<dim3(2 * 2, HH/8, NB), bm2>>>(p_e2clf, out_mask, p_mhh, p_mhh, 9);

    // hr_out = 2*hr_feat - carafe(hr_feat, softmax9(mask_hr), 3, 1) -> output 1
    carafe_s1_kernel<<<dim3(256/16, HH/4, NB), bm>>>(hr_feat, p_mhh, out_hr, 256);

    // lr_out = carafe(lr_feat, mask_lr_out, 5, 2) -> output 2
    carafe_s2_kernel<false, 16><<<dim3(2 * 16, HH/8, NB), bm2>>>(lr_feat, out_mask, nullptr, out_lr, 256);
}

// round 14
// speedup vs baseline: 2.0461x; 1.0048x over previous
#include <cuda_runtime.h>

// ---------------------------------------------------------------------------
// Problem constants (fixed shapes from setup_inputs)
// ---------------------------------------------------------------------------
#define NB   4
#define CIN  256          // CH == CL == 256
#define CCC  64           // compressed channels
#define HH   128
#define WW   128
#define HWX  (HH*WW)      // 16384
#define H2   64
#define W2   64
#define HW2  (H2*W2)      // 4096

// ---------------------------------------------------------------------------
// Device-global scratch (no cudaMalloc allowed)
// ---------------------------------------------------------------------------
__device__ float g_chf  [NB*CCC*HWX];   // 16 MB
__device__ float g_chf2 [NB*CCC*HWX];   // 16 MB
__device__ float g_clf  [NB*CCC*HW2];   // 4 MB
__device__ float g_mhh  [NB*9 *HWX];    // mask_hr_hr -> mask_hr (in-place add)
__device__ float g_mlh  [NB*25*HWX];    // mask_lr_hr -> mask_lr (in-place add)
__device__ float g_sm25 [NB*25*HWX];    // softmax(mask_lr_hr)
__device__ float g_mlll [NB*25*HW2];    // enc(clf)
__device__ float g_e2clf[NB*9 *HW2];    // enc2(clf)

// ---------------------------------------------------------------------------
// conv1x1 as SGEMM: Y[n][oc][p] = b[oc] + sum_c W[oc][c] * X[n][c][p]
// M=64, K=256; BN=256 pixels, BK=16; thread tile 8x8 (8 oc x 8 pixels)
// ---------------------------------------------------------------------------
__global__ void __launch_bounds__(256) conv1x1_kernel(
    const float* __restrict__ X, const float* __restrict__ Wt,
    const float* __restrict__ Bi, float* __restrict__ Y, int P)
{
    __shared__ float Ws[16][64];
    __shared__ float Xs[16][256];
    const int n  = blockIdx.z;
    const int p0 = blockIdx.x * 256;
    const int tid = threadIdx.x;
    const int tx = tid & 31;   // pixel group (8 px each)
    const int ty = tid >> 5;   // oc group (8 oc each)
    const float* Xn = X + (size_t)n * CIN * P;

    float acc[8][8];
#pragma unroll
    for (int i = 0; i < 8; i++)
#pragma unroll
        for (int j = 0; j < 8; j++) acc[i][j] = 0.f;

    for (int k0 = 0; k0 < CIN; k0 += 16) {
#pragma unroll
        for (int i = 0; i < 4; i++) {
            int idx = i * 256 + tid;
            int kk = idx >> 6, mm = idx & 63;
            Ws[kk][mm] = Wt[mm * CIN + k0 + kk];
        }
#pragma unroll
        for (int i = 0; i < 4; i++) {
            int idx = i * 256 + tid;
            int kk = idx >> 6;
            int pp = (idx & 63) << 2;
            *(float4*)&Xs[kk][pp] =
                *(const float4*)&Xn[(size_t)(k0 + kk) * P + p0 + pp];
        }
        __syncthreads();
#pragma unroll
        for (int k = 0; k < 16; k++) {
            float rw[8], rx[8];
            *(float4*)&rw[0] = *(float4*)&Ws[k][ty * 8];
            *(float4*)&rw[4] = *(float4*)&Ws[k][ty * 8 + 4];
            *(float4*)&rx[0] = *(float4*)&Xs[k][tx * 8];
            *(float4*)&rx[4] = *(float4*)&Xs[k][tx * 8 + 4];
#pragma unroll
            for (int i = 0; i < 8; i++)
#pragma unroll
                for (int j = 0; j < 8; j++)
                    acc[i][j] += rw[i] * rx[j];
        }
        __syncthreads();
    }

#pragma unroll
    for (int i = 0; i < 8; i++) {
        int oc = ty * 8 + i;
        float bv = Bi[oc];
        size_t base = ((size_t)n * CCC + oc) * P + p0 + tx * 8;
        float4 v0 = make_float4(acc[i][0]+bv, acc[i][1]+bv, acc[i][2]+bv, acc[i][3]+bv);
        float4 v1 = make_float4(acc[i][4]+bv, acc[i][5]+bv, acc[i][6]+bv, acc[i][7]+bv);
        *(float4*)&Y[base]     = v0;
        *(float4*)&Y[base + 4] = v1;
    }
}

// ---------------------------------------------------------------------------
// conv3x3, pad=1, Cin=64. Output channels split across blocks in chunks of
// K2C (blockIdx.x). All chunk weights preloaded to smem once; input tile is
// double-buffered -> ONE __syncthreads per channel.
// blockDim(32,4); thread produces XPT consecutive x-pixels in one row.
// ---------------------------------------------------------------------------
template<int K2C, int K2, int XPT>
__global__ void __launch_bounds__(128) conv3x3_kernel(
    const float* __restrict__ X, const float* __restrict__ Wt,
    const float* __restrict__ Bi, float* __restrict__ Y,
    int Hi, int Wi)
{
    const int TW = 32 * XPT;          // == Wi
    const int n   = blockIdx.z;
    const int oc0 = blockIdx.x * K2C;
    const int y0  = blockIdx.y * 4;
    const int tx = threadIdx.x, ty = threadIdx.y;
    const int tid = ty * 32 + tx;

    __shared__ float ws[CCC * K2C * 9];
    __shared__ float tile[2][6][32 * XPT + 8];

    // preload all weights for this output-channel chunk (once)
    for (int i = tid; i < CCC * K2C * 9; i += 128) {
        int c = i / (K2C * 9);
        int r = i % (K2C * 9);
        int o = r / 9, k = r % 9;
        ws[i] = Wt[((oc0 + o) * CCC + c) * 9 + k];
    }

    float acc[K2C][XPT];
#pragma unroll
    for (int o = 0; o < K2C; o++)
#pragma unroll
        for (int j = 0; j < XPT; j++) acc[o][j] = 0.f;

    const int HWi = Hi * Wi;
    const float* Xn = X + (size_t)n * CCC * HWi;

#pragma unroll 1
    for (int c = 0; c < CCC; c++) {
        const float* Xc = Xn + (size_t)c * HWi;
        float (*tb)[32 * XPT + 8] = tile[c & 1];
        for (int i = tid; i < 6 * (TW + 2); i += 128) {
            int r = i / (TW + 2), cc2 = i % (TW + 2);
            int gy = y0 - 1 + r, gx = cc2 - 1;
            float v = 0.f;
            if ((unsigned)gy < (unsigned)Hi && (unsigned)gx < (unsigned)Wi)
                v = Xc[gy * Wi + gx];
            tb[r][cc2] = v;
        }
        __syncthreads();   // covers ws preload on first iteration too

        float win[3][XPT + 2];
#pragma unroll
        for (int r = 0; r < 3; r++)
#pragma unroll
            for (int j = 0; j < XPT + 2; j++)
                win[r][j] = tb[ty + r][tx * XPT + j];

        const float* wc = &ws[c * K2C * 9];
#pragma unroll
        for (int o = 0; o < K2C; o++)
#pragma unroll
            for (int r = 0; r < 3; r++)
#pragma unroll
                for (int dc = 0; dc < 3; dc++) {
                    float w = wc[o * 9 + r * 3 + dc];
#pragma unroll
                    for (int j = 0; j < XPT; j++)
                        acc[o][j] += w * win[r][j + dc];
                }
    }

    const int y = y0 + ty;
#pragma unroll
    for (int o = 0; o < K2C; o++) {
        float bv = Bi[oc0 + o];
        size_t base = (((size_t)n * K2 + oc0 + o) * Hi + y) * Wi + tx * XPT;
#pragma unroll
        for (int j = 0; j < XPT; j++) Y[base + j] = acc[o][j] + bv;
    }
}

// ---------------------------------------------------------------------------
// per-pixel softmax over K2 channel axis. Layout [n][K2][HWX].
// ---------------------------------------------------------------------------
template<int K2>
__global__ void softmax_kernel(const float* __restrict__ X, float* __restrict__ Y)
{
    const int p = blockIdx.x * 256 + threadIdx.x;
    const int n = blockIdx.z;
    const float* xp = X + (size_t)n * K2 * HWX + p;
    float v[K2];
    float mx = -1e30f;
#pragma unroll
    for (int j = 0; j < K2; j++) { v[j] = xp[(size_t)j * HWX]; mx = fmaxf(mx, v[j]); }
    float s = 0.f;
#pragma unroll
    for (int j = 0; j < K2; j++) { v[j] = __expf(v[j] - mx); s += v[j]; }
    float inv = 1.f / s;
    float* yp = Y + (size_t)n * K2 * HWX + p;
#pragma unroll
    for (int j = 0; j < K2; j++) yp[(size_t)j * HWX] = v[j] * inv;
}

// ---------------------------------------------------------------------------
// CARAFE scale=1, k=3, fused residual + INLINE softmax over the 9 raw mask
// logits: Y = 2*F - sum_j softmax(m)[j]*window[j].
// Channel-chunked: blockIdx.x selects 16 channels. Double-buffered tile.
// ---------------------------------------------------------------------------
__global__ void __launch_bounds__(128) carafe_s1_kernel(
    const float* __restrict__ F, const float* __restrict__ M,
    float* __restrict__ Y, int C)
{
    const int n  = blockIdx.z;
    const int y0 = blockIdx.y * 4;
    const int c0 = blockIdx.x * 16;
    const int tx = threadIdx.x, ty = threadIdx.y;
    const int tid = ty * 32 + tx;
    __shared__ float tile[2][6][136];

    const int y  = y0 + ty;
    const int xb = tx * 4;

    // raw mask logits for this thread's 4 pixels -> softmax in registers
    float mk[9][4];
    const float* Mn = M + (size_t)n * 9 * HWX;
#pragma unroll
    for (int j = 0; j < 9; j++) {
        float4 m4 = *(const float4*)&Mn[(size_t)j * HWX + y * WW + xb];
        mk[j][0] = m4.x; mk[j][1] = m4.y; mk[j][2] = m4.z; mk[j][3] = m4.w;
    }
#pragma unroll
    for (int px = 0; px < 4; px++) {
        float mx = mk[0][px];
#pragma unroll
        for (int j = 1; j < 9; j++) mx = fmaxf(mx, mk[j][px]);
        float s = 0.f;
#pragma unroll
        for (int j = 0; j < 9; j++) { mk[j][px] = __expf(mk[j][px] - mx); s += mk[j][px]; }
        float inv = 1.f / s;
#pragma unroll
        for (int j = 0; j < 9; j++) mk[j][px] *= inv;
    }

    const float* Fn = F + (size_t)n * C * HWX;
    float* Yn = Y + (size_t)n * C * HWX;

#pragma unroll 1
    for (int cc = 0; cc < 16; cc++) {
        const int c = c0 + cc;
        const float* Fc = Fn + (size_t)c * HWX;
        float (*tb)[136] = tile[cc & 1];
        for (int i = tid; i < 6 * 130; i += 128) {
            int r = i / 130, cc2 = i % 130;
            int gy = y0 - 1 + r, gx = cc2 - 1;
            float v = 0.f;
            if ((unsigned)gy < HH && (unsigned)gx < WW) v = Fc[gy * WW + gx];
            tb[r][cc2] = v;
        }
        __syncthreads();

        float win[3][6];
#pragma unroll
        for (int r = 0; r < 3; r++)
#pragma unroll
            for (int j = 0; j < 6; j++)
                win[r][j] = tb[ty + r][xb + j];

        float out[4];
#pragma unroll
        for (int px = 0; px < 4; px++) out[px] = 2.f * win[1][px + 1];
#pragma unroll
        for (int r = 0; r < 3; r++)
#pragma unroll
            for (int dc = 0; dc < 3; dc++)
#pragma unroll
                for (int px = 0; px < 4; px++)
                    out[px] -= mk[r * 3 + dc][px] * win[r][px + dc];

        *(float4*)&Yn[(size_t)c * HWX + y * WW + xb] =
            make_float4(out[0], out[1], out[2], out[3]);
    }
}

// ---------------------------------------------------------------------------
// CARAFE scale=2, k=5. F:[n][C][64][64], M normalized:[n][25][128][128].
// Channel-chunked (CC per block) + double-buffered tile.
// blockIdx.x encodes (x-tile in bit0, channel chunk above).
// ---------------------------------------------------------------------------
template<bool ADD, int CC>
__global__ void __launch_bounds__(256) carafe_s2_kernel(
    const float* __restrict__ F, const float* __restrict__ M,
    const float* __restrict__ B, float* __restrict__ Y, int C)
{
    const int n  = blockIdx.z;
    const int xt = blockIdx.x & 1;
    const int c0 = (blockIdx.x >> 1) * CC;
    const int x0 = xt * 64, y0 = blockIdx.y * 8;
    const int tx = threadIdx.x, ty = threadIdx.y;
    const int tid = ty * 32 + tx;
    const int xo = x0 + tx * 2;
    const int yo = y0 + ty;

    __shared__ float tile[2][8][36];

    float mk0[25], mk1[25];
    const float* Mn = M + (size_t)n * 25 * HWX;
#pragma unroll
    for (int j = 0; j < 25; j++) {
        float2 m2 = *(const float2*)&Mn[(size_t)j * HWX + yo * WW + xo];
        mk0[j] = m2.x; mk1[j] = m2.y;
    }

    const int ylb = y0 / 2 - 2, xlb = x0 / 2 - 2;
    const int rb  = ty >> 1;
    const float* Fn = F + (size_t)n * C * HW2;
    const int cend = (c0 + CC < C) ? c0 + CC : C;

#pragma unroll 1
    for (int c = c0; c < cend; c++) {
        const float* Fc = Fn + (size_t)c * HW2;
        float (*tb)[36] = tile[c & 1];
        for (int i = tid; i < 8 * 36; i += 256) {
            int r = i / 36, cc2 = i % 36;
            int gy = ylb + r, gx = xlb + cc2;
            float v = 0.f;
            if ((unsigned)gy < H2 && (unsigned)gx < W2) v = Fc[gy * W2 + gx];
            tb[r][cc2] = v;
        }
        __syncthreads();

        float a0 = 0.f, a1 = 0.f;
#pragma unroll
        for (int ki = 0; ki < 5; ki++)
#pragma unroll
            for (int kj = 0; kj < 5; kj++) {
                float v = tb[rb + ki][tx + kj];
                a0 += v * mk0[ki * 5 + kj];
                a1 += v * mk1[ki * 5 + kj];
            }

        size_t oidx = (((size_t)n * C + c) * HH + yo) * WW + xo;
        if (ADD) {
            float2 b2 = *(const float2*)&B[oidx];
            a0 += b2.x; a1 += b2.y;
        }
        *(float2*)&Y[oidx] = make_float2(a0, a1);
    }
}

// ---------------------------------------------------------------------------
// Orchestration (graph-capturable: kernel launches only)
// ---------------------------------------------------------------------------
extern "C" void kernel_launch(void* const* d_in, const int* in_sizes, int n_in,
                              void* d_out, int out_size)
{
    const float* hr_feat = (const float*)d_in[0];
    const float* lr_feat = (const float*)d_in[1];
    const float* hr_w    = (const float*)d_in[2];
    const float* hr_b    = (const float*)d_in[3];
    const float* lr_w    = (const float*)d_in[4];
    const float* lr_b    = (const float*)d_in[5];
    const float* enc_w   = (const float*)d_in[6];
    const float* enc_b   = (const float*)d_in[7];
    const float* enc2_w  = (const float*)d_in[8];
    const float* enc2_b  = (const float*)d_in[9];
    float* out = (float*)d_out;

    float *p_chf, *p_chf2, *p_clf, *p_mhh, *p_mlh, *p_sm25, *p_mlll, *p_e2clf;
    cudaGetSymbolAddress((void**)&p_chf,   g_chf);
    cudaGetSymbolAddress((void**)&p_chf2,  g_chf2);
    cudaGetSymbolAddress((void**)&p_clf,   g_clf);
    cudaGetSymbolAddress((void**)&p_mhh,   g_mhh);
    cudaGetSymbolAddress((void**)&p_mlh,   g_mlh);
    cudaGetSymbolAddress((void**)&p_sm25,  g_sm25);
    cudaGetSymbolAddress((void**)&p_mlll,  g_mlll);
    cudaGetSymbolAddress((void**)&p_e2clf, g_e2clf);

    const size_t MASK_SZ = (size_t)NB * 25 * HWX;
    const size_t FEAT_SZ = (size_t)NB * 256 * HWX;
    float* out_mask = out;                          // mask_lr_out
    float* out_hr   = out + MASK_SZ;                // hr_out
    float* out_lr   = out + MASK_SZ + FEAT_SZ;      // lr_out

    dim3 bm(32, 4), bm2(32, 8);

    // chf = conv1x1(hr_feat), clf = conv1x1(lr_feat)
    conv1x1_kernel<<<dim3(HWX/256, 1, NB), 256>>>(hr_feat, hr_w, hr_b, p_chf, HWX);
    conv1x1_kernel<<<dim3(HW2/256, 1, NB), 256>>>(lr_feat, lr_w, lr_b, p_clf, HW2);

    // mask_hr_hr = enc2(chf)
    conv3x3_kernel<3, 9, 4><<<dim3(3, HH/4, NB), bm>>>(p_chf, enc2_w, enc2_b, p_mhh, HH, WW);

    // chf = 2*chf - carafe(chf, softmax9(mask_hr_hr), 3, 1)   (softmax inlined)
    carafe_s1_kernel<<<dim3(CCC/16, HH/4, NB), bm>>>(p_chf, p_mhh, p_chf2, CCC);

    // mask_lr_hr = enc(chf'); mask_lr_lr_lr = enc(clf)
    conv3x3_kernel<5, 25, 4><<<dim3(5, HH/4, NB), bm>>>(p_chf2, enc_w, enc_b, p_mlh, HH, WW);
    conv3x3_kernel<5, 25, 2><<<dim3(5, H2/4, NB), bm>>>(p_clf, enc_w, enc_b, p_mlll, H2, W2);

    // mask_lr = mask_lr_hr + carafe(mask_lr_lr_lr, softmax25(mask_lr_hr), 5, 2)
    softmax_kernel<25><<<dim3(HWX/256, 1, NB), 256>>>(p_mlh, p_sm25);
    carafe_s2_kernel<true, 8><<<dim3(2 * 4, HH/8, NB), bm2>>>(p_mlll, p_sm25, p_mlh, p_mlh, 25);

    // mask_lr_out = softmax25(mask_lr) -> output 0 (also operand of last carafes)
    softmax_kernel<25><<<dim3(HWX/256, 1, NB), 256>>>(p_mlh, out_mask);

    // mask_hr = mask_hr_hr + carafe(enc2(clf), mask_lr_out, 5, 2)
    conv3x3_kernel<3, 9, 2><<<dim3(3, H2/4, NB), bm>>>(p_clf, enc2_w, enc2_b, p_e2clf, H2, W2);
    carafe_s2_kernel<true, 8><<<dim3(2 * 2, HH/8, NB), bm2>>>(p_e2clf, out_mask, p_mhh, p_mhh, 9);

    // hr_out = 2*hr_feat - carafe(hr_feat, softmax9(mask_hr), 3, 1) -> output 1
    carafe_s1_kernel<<<dim3(256/16, HH/4, NB), bm>>>(hr_feat, p_mhh, out_hr, 256);

    // lr_out = carafe(lr_feat, mask_lr_out, 5, 2) -> output 2
    carafe_s2_kernel<false, 16><<<dim3(2 * 16, HH/8, NB), bm2>>>(lr_feat, out_mask, nullptr, out_lr, 256);
}

// round 15
// speedup vs baseline: 3.7899x; 1.8523x over previous
#include <cuda_runtime.h>

// ---------------------------------------------------------------------------
// Problem constants (fixed shapes from setup_inputs)
// ---------------------------------------------------------------------------
#define NB   4
#define CIN  256          // CH == CL == 256
#define CCC  64           // compressed channels
#define HH   128
#define WW   128
#define HWX  (HH*WW)      // 16384
#define H2   64
#define W2   64
#define HW2  (H2*W2)      // 4096

// ---------------------------------------------------------------------------
// Device-global scratch (no cudaMalloc allowed)
// ---------------------------------------------------------------------------
__device__ float g_chf  [NB*CCC*HWX];   // 16 MB
__device__ float g_chf2 [NB*CCC*HWX];   // 16 MB
__device__ float g_clf  [NB*CCC*HW2];   // 4 MB
__device__ float g_mhh  [NB*9 *HWX];    // mask_hr_hr -> mask_hr (in-place add)
__device__ float g_mlh  [NB*25*HWX];    // mask_lr_hr (raw logits)
__device__ float g_mlh2 [NB*25*HWX];    // mask_lr = mask_lr_hr + carafe(...)
__device__ float g_mlll [NB*25*HW2];    // enc(clf)
__device__ float g_e2clf[NB*9 *HW2];    // enc2(clf)

// ---------------------------------------------------------------------------
// conv1x1 as SGEMM: Y[n][oc][p] = b[oc] + sum_c W[oc][c] * X[n][c][p]
// M=64, K=256; BN=256 pixels, BK=16; thread tile 8x8 (8 oc x 8 pixels)
// ---------------------------------------------------------------------------
__global__ void __launch_bounds__(256) conv1x1_kernel(
    const float* __restrict__ X, const float* __restrict__ Wt,
    const float* __restrict__ Bi, float* __restrict__ Y, int P)
{
    __shared__ float Ws[16][64];
    __shared__ float Xs[16][256];
    const int n  = blockIdx.z;
    const int p0 = blockIdx.x * 256;
    const int tid = threadIdx.x;
    const int tx = tid & 31;   // pixel group (8 px each)
    const int ty = tid >> 5;   // oc group (8 oc each)
    const float* Xn = X + (size_t)n * CIN * P;

    float acc[8][8];
#pragma unroll
    for (int i = 0; i < 8; i++)
#pragma unroll
        for (int j = 0; j < 8; j++) acc[i][j] = 0.f;

    for (int k0 = 0; k0 < CIN; k0 += 16) {
#pragma unroll
        for (int i = 0; i < 4; i++) {
            int idx = i * 256 + tid;
            int kk = idx >> 6, mm = idx & 63;
            Ws[kk][mm] = Wt[mm * CIN + k0 + kk];
        }
#pragma unroll
        for (int i = 0; i < 4; i++) {
            int idx = i * 256 + tid;
            int kk = idx >> 6;
            int pp = (idx & 63) << 2;
            *(float4*)&Xs[kk][pp] =
                *(const float4*)&Xn[(size_t)(k0 + kk) * P + p0 + pp];
        }
        __syncthreads();
#pragma unroll
        for (int k = 0; k < 16; k++) {
            float rw[8], rx[8];
            *(float4*)&rw[0] = *(float4*)&Ws[k][ty * 8];
            *(float4*)&rw[4] = *(float4*)&Ws[k][ty * 8 + 4];
            *(float4*)&rx[0] = *(float4*)&Xs[k][tx * 8];
            *(float4*)&rx[4] = *(float4*)&Xs[k][tx * 8 + 4];
#pragma unroll
            for (int i = 0; i < 8; i++)
#pragma unroll
                for (int j = 0; j < 8; j++)
                    acc[i][j] += rw[i] * rx[j];
        }
        __syncthreads();
    }

#pragma unroll
    for (int i = 0; i < 8; i++) {
        int oc = ty * 8 + i;
        float bv = Bi[oc];
        size_t base = ((size_t)n * CCC + oc) * P + p0 + tx * 8;
        float4 v0 = make_float4(acc[i][0]+bv, acc[i][1]+bv, acc[i][2]+bv, acc[i][3]+bv);
        float4 v1 = make_float4(acc[i][4]+bv, acc[i][5]+bv, acc[i][6]+bv, acc[i][7]+bv);
        *(float4*)&Y[base]     = v0;
        *(float4*)&Y[base + 4] = v1;
    }
}

// ---------------------------------------------------------------------------
// Row-window loader: 3 rows x (XPT+2) window around (y, tx*XPT) built from
// predicated vector loads + warp shuffles for the +/-1 halo. Sync-free.
// ---------------------------------------------------------------------------
template<int XPT>
__device__ __forceinline__ void load_win3(
    const float* __restrict__ Xc, int y, int Hi, int Wi, int tx,
    float win[3][XPT + 2])
{
#pragma unroll
    for (int r = 0; r < 3; r++) {
        int gy = y - 1 + r;
        bool ok = (unsigned)gy < (unsigned)Hi;
        if (XPT == 4) {
            float4 v = make_float4(0.f, 0.f, 0.f, 0.f);
            if (ok) v = *(const float4*)(Xc + gy * Wi + tx * 4);
            float lw = __shfl_up_sync(0xffffffffu, v.w, 1);
            float rw = __shfl_down_sync(0xffffffffu, v.x, 1);
            win[r][0] = (tx == 0) ? 0.f : lw;
            win[r][1] = v.x; win[r][2] = v.y; win[r][3] = v.z; win[r][4] = v.w;
            win[r][5] = (tx == 31) ? 0.f : rw;
        } else {
            float2 v = make_float2(0.f, 0.f);
            if (ok) v = *(const float2*)(Xc + gy * Wi + tx * 2);
            float lw = __shfl_up_sync(0xffffffffu, v.y, 1);
            float rw = __shfl_down_sync(0xffffffffu, v.x, 1);
            win[r][0] = (tx == 0) ? 0.f : lw;
            win[r][1] = v.x; win[r][2] = v.y;
            win[r][3] = (tx == 31) ? 0.f : rw;
        }
    }
}

// ---------------------------------------------------------------------------
// conv3x3, pad=1, Cin=64. Output channels split across blocks in chunks of
// K2C. Chunk weights preloaded to smem ONCE (single barrier); mainloop is
// sync-free: per channel 3 vector loads + shuffles.
// blockDim(32,4); thread produces XPT consecutive x-pixels in one row.
// ---------------------------------------------------------------------------
template<int K2C, int K2, int XPT>
__global__ void __launch_bounds__(128) conv3x3_kernel(
    const float* __restrict__ X, const float* __restrict__ Wt,
    const float* __restrict__ Bi, float* __restrict__ Y,
    int Hi, int Wi)
{
    const int n   = blockIdx.z;
    const int oc0 = blockIdx.x * K2C;
    const int y0  = blockIdx.y * 4;
    const int tx = threadIdx.x, ty = threadIdx.y;
    const int tid = ty * 32 + tx;
    const int y = y0 + ty;

    __shared__ float ws[CCC * K2C * 9];
    for (int i = tid; i < CCC * K2C * 9; i += 128) {
        int c = i / (K2C * 9);
        int r = i % (K2C * 9);
        int o = r / 9, k = r % 9;
        ws[i] = Wt[((oc0 + o) * CCC + c) * 9 + k];
    }
    __syncthreads();   // only barrier in the kernel

    float acc[K2C][XPT];
#pragma unroll
    for (int o = 0; o < K2C; o++)
#pragma unroll
        for (int j = 0; j < XPT; j++) acc[o][j] = 0.f;

    const int HWi = Hi * Wi;
    const float* Xn = X + (size_t)n * CCC * HWi;

#pragma unroll 2
    for (int c = 0; c < CCC; c++) {
        float win[3][XPT + 2];
        load_win3<XPT>(Xn + (size_t)c * HWi, y, Hi, Wi, tx, win);

        const float* wc = &ws[c * K2C * 9];
#pragma unroll
        for (int o = 0; o < K2C; o++)
#pragma unroll
            for (int r = 0; r < 3; r++)
#pragma unroll
                for (int dc = 0; dc < 3; dc++) {
                    float w = wc[o * 9 + r * 3 + dc];
#pragma unroll
                    for (int j = 0; j < XPT; j++)
                        acc[o][j] += w * win[r][j + dc];
                }
    }

#pragma unroll
    for (int o = 0; o < K2C; o++) {
        float bv = Bi[oc0 + o];
        size_t base = (((size_t)n * K2 + oc0 + o) * Hi + y) * Wi + tx * XPT;
#pragma unroll
        for (int j = 0; j < XPT; j++) Y[base + j] = acc[o][j] + bv;
    }
}

// ---------------------------------------------------------------------------
// per-pixel softmax over K2 channel axis. Layout [n][K2][HWX].
// ---------------------------------------------------------------------------
template<int K2>
__global__ void softmax_kernel(const float* __restrict__ X, float* __restrict__ Y)
{
    const int p = blockIdx.x * 256 + threadIdx.x;
    const int n = blockIdx.z;
    const float* xp = X + (size_t)n * K2 * HWX + p;
    float v[K2];
    float mx = -1e30f;
#pragma unroll
    for (int j = 0; j < K2; j++) { v[j] = xp[(size_t)j * HWX]; mx = fmaxf(mx, v[j]); }
    float s = 0.f;
#pragma unroll
    for (int j = 0; j < K2; j++) { v[j] = __expf(v[j] - mx); s += v[j]; }
    float inv = 1.f / s;
    float* yp = Y + (size_t)n * K2 * HWX + p;
#pragma unroll
    for (int j = 0; j < K2; j++) yp[(size_t)j * HWX] = v[j] * inv;
}

// ---------------------------------------------------------------------------
// CARAFE scale=1, k=3, fused residual + INLINE softmax over the 9 raw mask
// logits: Y = 2*F - sum_j softmax(m)[j]*window[j].
// Sync-free, smem-free: direct row loads + shuffles. CCH channels per block.
// ---------------------------------------------------------------------------
template<int CCH>
__global__ void __launch_bounds__(128) carafe_s1_kernel(
    const float* __restrict__ F, const float* __restrict__ M,
    float* __restrict__ Y, int C)
{
    const int n  = blockIdx.z;
    const int y0 = blockIdx.y * 4;
    const int c0 = blockIdx.x * CCH;
    const int tx = threadIdx.x, ty = threadIdx.y;
    const int y  = y0 + ty;
    const int xb = tx * 4;

    // raw mask logits for this thread's 4 pixels -> softmax in registers
    float mk[9][4];
    const float* Mn = M + (size_t)n * 9 * HWX;
#pragma unroll
    for (int j = 0; j < 9; j++) {
        float4 m4 = *(const float4*)&Mn[(size_t)j * HWX + y * WW + xb];
        mk[j][0] = m4.x; mk[j][1] = m4.y; mk[j][2] = m4.z; mk[j][3] = m4.w;
    }
#pragma unroll
    for (int px = 0; px < 4; px++) {
        float mx = mk[0][px];
#pragma unroll
        for (int j = 1; j < 9; j++) mx = fmaxf(mx, mk[j][px]);
        float s = 0.f;
#pragma unroll
        for (int j = 0; j < 9; j++) { mk[j][px] = __expf(mk[j][px] - mx); s += mk[j][px]; }
        float inv = 1.f / s;
#pragma unroll
        for (int j = 0; j < 9; j++) mk[j][px] *= inv;
    }

    const float* Fn = F + (size_t)n * C * HWX;
    float* Yn = Y + (size_t)n * C * HWX;

#pragma unroll 2
    for (int cc = 0; cc < CCH; cc++) {
        const int c = c0 + cc;
        float win[3][6];
        load_win3<4>(Fn + (size_t)c * HWX, y, HH, WW, tx, win);

        float out[4];
#pragma unroll
        for (int px = 0; px < 4; px++) out[px] = 2.f * win[1][px + 1];
#pragma unroll
        for (int r = 0; r < 3; r++)
#pragma unroll
            for (int dc = 0; dc < 3; dc++)
#pragma unroll
                for (int px = 0; px < 4; px++)
                    out[px] -= mk[r * 3 + dc][px] * win[r][px + dc];

        *(float4*)&Yn[(size_t)c * HWX + y * WW + xb] =
            make_float4(out[0], out[1], out[2], out[3]);
    }
}

// ---------------------------------------------------------------------------
// CARAFE scale=2, k=5. F:[n][C][64][64], M:[n][25][128][128].
// SMAX: M holds raw logits, softmax applied in registers.
// ADD:  Y = B + carafe (B read only at own element -> in-place safe).
// Channel-chunked (CC per block) + double-buffered tile.
// blockIdx.x encodes (x-tile in bit0, channel chunk above).
// ---------------------------------------------------------------------------
template<bool ADD, bool SMAX, int CC>
__global__ void __launch_bounds__(256) carafe_s2_kernel(
    const float* __restrict__ F, const float* __restrict__ M,
    const float* __restrict__ B, float* __restrict__ Y, int C)
{
    const int n  = blockIdx.z;
    const int xt = blockIdx.x & 1;
    const int c0 = (blockIdx.x >> 1) * CC;
    const int x0 = xt * 64, y0 = blockIdx.y * 8;
    const int tx = threadIdx.x, ty = threadIdx.y;
    const int tid = ty * 32 + tx;
    const int xo = x0 + tx * 2;
    const int yo = y0 + ty;

    __shared__ float tile[2][8][36];

    float mk0[25], mk1[25];
    const float* Mn = M + (size_t)n * 25 * HWX;
#pragma unroll
    for (int j = 0; j < 25; j++) {
        float2 m2 = *(const float2*)&Mn[(size_t)j * HWX + yo * WW + xo];
        mk0[j] = m2.x; mk1[j] = m2.y;
    }
    if (SMAX) {
        float mx0 = mk0[0], mx1 = mk1[0];
#pragma unroll
        for (int j = 1; j < 25; j++) { mx0 = fmaxf(mx0, mk0[j]); mx1 = fmaxf(mx1, mk1[j]); }
        float s0 = 0.f, s1 = 0.f;
#pragma unroll
        for (int j = 0; j < 25; j++) {
            mk0[j] = __expf(mk0[j] - mx0); s0 += mk0[j];
            mk1[j] = __expf(mk1[j] - mx1); s1 += mk1[j];
        }
        float i0 = 1.f / s0, i1 = 1.f / s1;
#pragma unroll
        for (int j = 0; j < 25; j++) { mk0[j] *= i0; mk1[j] *= i1; }
    }

    const int ylb = y0 / 2 - 2, xlb = x0 / 2 - 2;
    const int rb  = ty >> 1;
    const float* Fn = F + (size_t)n * C * HW2;
    const int cend = (c0 + CC < C) ? c0 + CC : C;

#pragma unroll 1
    for (int c = c0; c < cend; c++) {
        const float* Fc = Fn + (size_t)c * HW2;
        float (*tb)[36] = tile[c & 1];
        for (int i = tid; i < 8 * 36; i += 256) {
            int r = i / 36, cc2 = i % 36;
            int gy = ylb + r, gx = xlb + cc2;
            float v = 0.f;
            if ((unsigned)gy < H2 && (unsigned)gx < W2) v = Fc[gy * W2 + gx];
            tb[r][cc2] = v;
        }
        __syncthreads();

        float a0 = 0.f, a1 = 0.f;
#pragma unroll
        for (int ki = 0; ki < 5; ki++)
#pragma unroll
            for (int kj = 0; kj < 5; kj++) {
                float v = tb[rb + ki][tx + kj];
                a0 += v * mk0[ki * 5 + kj];
                a1 += v * mk1[ki * 5 + kj];
            }

        size_t oidx = (((size_t)n * C + c) * HH + yo) * WW + xo;
        if (ADD) {
            float2 b2 = *(const float2*)&B[oidx];
            a0 += b2.x; a1 += b2.y;
        }
        *(float2*)&Y[oidx] = make_float2(a0, a1);
    }
}

// ---------------------------------------------------------------------------
// Orchestration (graph-capturable: kernel launches only)
// ---------------------------------------------------------------------------
extern "C" void kernel_launch(void* const* d_in, const int* in_sizes, int n_in,
                              void* d_out, int out_size)
{
    const float* hr_feat = (const float*)d_in[0];
    const float* lr_feat = (const float*)d_in[1];
    const float* hr_w    = (const float*)d_in[2];
    const float* hr_b    = (const float*)d_in[3];
    const float* lr_w    = (const float*)d_in[4];
    const float* lr_b    = (const float*)d_in[5];
    const float* enc_w   = (const float*)d_in[6];
    const float* enc_b   = (const float*)d_in[7];
    const float* enc2_w  = (const float*)d_in[8];
    const float* enc2_b  = (const float*)d_in[9];
    float* out = (float*)d_out;

    float *p_chf, *p_chf2, *p_clf, *p_mhh, *p_mlh, *p_mlh2, *p_mlll, *p_e2clf;
    cudaGetSymbolAddress((void**)&p_chf,   g_chf);
    cudaGetSymbolAddress((void**)&p_chf2,  g_chf2);
    cudaGetSymbolAddress((void**)&p_clf,   g_clf);
    cudaGetSymbolAddress((void**)&p_mhh,   g_mhh);
    cudaGetSymbolAddress((void**)&p_mlh,   g_mlh);
    cudaGetSymbolAddress((void**)&p_mlh2,  g_mlh2);
    cudaGetSymbolAddress((void**)&p_mlll,  g_mlll);
    cudaGetSymbolAddress((void**)&p_e2clf, g_e2clf);

    const size_t MASK_SZ = (size_t)NB * 25 * HWX;
    const size_t FEAT_SZ = (size_t)NB * 256 * HWX;
    float* out_mask = out;                          // mask_lr_out
    float* out_hr   = out + MASK_SZ;                // hr_out
    float* out_lr   = out + MASK_SZ + FEAT_SZ;      // lr_out

    dim3 bm(32, 4), bm2(32, 8);

    // chf = conv1x1(hr_feat), clf = conv1x1(lr_feat)
    conv1x1_kernel<<<dim3(HWX/256, 1, NB), 256>>>(hr_feat, hr_w, hr_b, p_chf, HWX);
    conv1x1_kernel<<<dim3(HW2/256, 1, NB), 256>>>(lr_feat, lr_w, lr_b, p_clf, HW2);

    // mask_hr_hr = enc2(chf)
    conv3x3_kernel<3, 9, 4><<<dim3(3, HH/4, NB), bm>>>(p_chf, enc2_w, enc2_b, p_mhh, HH, WW);

    // chf' = 2*chf - carafe(chf, softmax9(mask_hr_hr), 3, 1)   (softmax inlined)
    carafe_s1_kernel<8><<<dim3(CCC/8, HH/4, NB), bm>>>(p_chf, p_mhh, p_chf2, CCC);

    // mask_lr_hr = enc(chf'); mask_lr_lr_lr = enc(clf)
    conv3x3_kernel<5, 25, 4><<<dim3(5, HH/4, NB), bm>>>(p_chf2, enc_w, enc_b, p_mlh, HH, WW);
    conv3x3_kernel<5, 25, 2><<<dim3(5, H2/4, NB), bm>>>(p_clf, enc_w, enc_b, p_mlll, H2, W2);

    // mask_lr = mask_lr_hr + carafe(mask_lr_lr_lr, softmax25(mask_lr_hr), 5, 2)
    // (softmax inlined; reads raw p_mlh, writes p_mlh2 -> no race)
    carafe_s2_kernel<true, true, 4><<<dim3(2 * 7, HH/8, NB), bm2>>>(p_mlll, p_mlh, p_mlh, p_mlh2, 25);

    // mask_lr_out = softmax25(mask_lr) -> output 0 (also operand of last carafes)
    softmax_kernel<25><<<dim3(HWX/256, 1, NB), 256>>>(p_mlh2, out_mask);

    // mask_hr = mask_hr_hr + carafe(enc2(clf), mask_lr_out, 5, 2)
    conv3x3_kernel<3, 9, 2><<<dim3(3, H2/4, NB), bm>>>(p_clf, enc2_w, enc2_b, p_e2clf, H2, W2);
    carafe_s2_kernel<true, false, 2><<<dim3(2 * 5, HH/8, NB), bm2>>>(p_e2clf, out_mask, p_mhh, p_mhh, 9);

    // hr_out = 2*hr_feat - carafe(hr_feat, softmax9(mask_hr), 3, 1) -> output 1
    carafe_s1_kernel<8><<<dim3(256/8, HH/4, NB), bm>>>(hr_feat, p_mhh, out_hr, 256);

    // lr_out = carafe(lr_feat, mask_lr_out, 5, 2) -> output 2
    carafe_s2_kernel<false, false, 16><<<dim3(2 * 16, HH/8, NB), bm2>>>(lr_feat, out_mask, nullptr, out_lr, 256);
}

// round 16
// speedup vs baseline: 3.8111x; 1.0056x over previous
#include <cuda_runtime.h>

// ---------------------------------------------------------------------------
// Problem constants (fixed shapes from setup_inputs)
// ---------------------------------------------------------------------------
#define NB   4
#define CIN  256          // CH == CL == 256
#define CCC  64           // compressed channels
#define HH   128
#define WW   128
#define HWX  (HH*WW)      // 16384
#define H2   64
#define W2   64
#define HW2  (H2*W2)      // 4096

typedef unsigned long long u64x;

// packed fp32x2 helpers (Blackwell FFMA2 path — only reachable via PTX)
__device__ __forceinline__ u64x pk2(float lo, float hi) {
    u64x r; asm("mov.b64 %0, {%1, %2};" : "=l"(r) : "f"(lo), "f"(hi)); return r;
}
__device__ __forceinline__ float2 up2(u64x v) {
    float2 f; asm("mov.b64 {%0, %1}, %2;" : "=f"(f.x), "=f"(f.y) : "l"(v)); return f;
}
__device__ __forceinline__ u64x fma2(u64x a, u64x b, u64x c) {
    u64x d; asm("fma.rn.f32x2 %0, %1, %2, %3;" : "=l"(d) : "l"(a), "l"(b), "l"(c)); return d;
}

// ---------------------------------------------------------------------------
// Device-global scratch (no cudaMalloc allowed)
// ---------------------------------------------------------------------------
__device__ float g_chf  [NB*CCC*HWX];   // 16 MB
__device__ float g_chf2 [NB*CCC*HWX];   // 16 MB
__device__ float g_clf  [NB*CCC*HW2];   // 4 MB
__device__ float g_mhh  [NB*9 *HWX];    // mask_hr_hr -> mask_hr (in-place add)
__device__ float g_mlh  [NB*25*HWX];    // mask_lr_hr (raw logits)
__device__ float g_mlh2 [NB*25*HWX];    // mask_lr
__device__ float g_mlll [NB*25*HW2];    // enc(clf)
__device__ float g_e2clf[NB*9 *HW2];    // enc2(clf)

// ---------------------------------------------------------------------------
// conv1x1 as SGEMM: Y[n][oc][p] = b[oc] + sum_c W[oc][c] * X[n][c][p]
// M=64, K=256; BN=256 pixels, BK=16; thread tile 8 oc x 8 px.
// Double-buffered smem (1 barrier per K-chunk) + FFMA2 inner product.
// ---------------------------------------------------------------------------
__global__ void __launch_bounds__(256) conv1x1_kernel(
    const float* __restrict__ X, const float* __restrict__ Wt,
    const float* __restrict__ Bi, float* __restrict__ Y, int P)
{
    __shared__ float Ws[2][16][64];
    __shared__ float Xs[2][16][256];
    const int n  = blockIdx.z;
    const int p0 = blockIdx.x * 256;
    const int tid = threadIdx.x;
    const int tx = tid & 31;   // pixel group (8 px each)
    const int ty = tid >> 5;   // oc group (8 oc each)
    const float* Xn = X + (size_t)n * CIN * P;

    // per-thread load coordinates (same for every chunk)
    const int wk = tid >> 6, wm = tid & 63;           // W: 4 rows x 64, 4 iters
    const int xk = tid >> 6;                          // X: row within 16 (4 iters of +4)
    const int xp = (tid & 63) << 2;                   // X: pixel*4

    u64x acc2[8][4];
#pragma unroll
    for (int i = 0; i < 8; i++)
#pragma unroll
        for (int j = 0; j < 4; j++) acc2[i][j] = 0ULL;

    // load chunk 0
#pragma unroll
    for (int i = 0; i < 4; i++)
        Ws[0][wk + i * 4][wm] = Wt[wm * CIN + wk + i * 4];
#pragma unroll
    for (int i = 0; i < 4; i++)
        *(float4*)&Xs[0][xk + i * 4][xp] =
            *(const float4*)&Xn[(size_t)(xk + i * 4) * P + p0 + xp];
    __syncthreads();

#pragma unroll 1
    for (int k0 = 0; k0 < 16; k0++) {
        const int buf = k0 & 1;
        float  wpre[4];
        float4 xpre[4];
        if (k0 < 15) {
            int kb = (k0 + 1) * 16;
#pragma unroll
            for (int i = 0; i < 4; i++)
                wpre[i] = Wt[wm * CIN + kb + wk + i * 4];
#pragma unroll
            for (int i = 0; i < 4; i++)
                xpre[i] = *(const float4*)&Xn[(size_t)(kb + xk + i * 4) * P + p0 + xp];
        }

#pragma unroll
        for (int k = 0; k < 16; k++) {
            float rw[8], rx[8];
            *(float4*)&rw[0] = *(float4*)&Ws[buf][k][ty * 8];
            *(float4*)&rw[4] = *(float4*)&Ws[buf][k][ty * 8 + 4];
            *(float4*)&rx[0] = *(float4*)&Xs[buf][k][tx * 8];
            *(float4*)&rx[4] = *(float4*)&Xs[buf][k][tx * 8 + 4];
            u64x x2[4];
#pragma unroll
            for (int j = 0; j < 4; j++) x2[j] = pk2(rx[2*j], rx[2*j+1]);
#pragma unroll
            for (int i = 0; i < 8; i++) {
                u64x w2 = pk2(rw[i], rw[i]);
#pragma unroll
                for (int j = 0; j < 4; j++)
                    acc2[i][j] = fma2(w2, x2[j], acc2[i][j]);
            }
        }

        if (k0 < 15) {
            const int nb = buf ^ 1;
#pragma unroll
            for (int i = 0; i < 4; i++) Ws[nb][wk + i * 4][wm] = wpre[i];
#pragma unroll
            for (int i = 0; i < 4; i++) *(float4*)&Xs[nb][xk + i * 4][xp] = xpre[i];
        }
        __syncthreads();
    }

#pragma unroll
    for (int i = 0; i < 8; i++) {
        int oc = ty * 8 + i;
        float bv = Bi[oc];
        size_t base = ((size_t)n * CCC + oc) * P + p0 + tx * 8;
        float2 a0 = up2(acc2[i][0]), a1 = up2(acc2[i][1]);
        float2 a2 = up2(acc2[i][2]), a3 = up2(acc2[i][3]);
        *(float4*)&Y[base]     = make_float4(a0.x+bv, a0.y+bv, a1.x+bv, a1.y+bv);
        *(float4*)&Y[base + 4] = make_float4(a2.x+bv, a2.y+bv, a3.x+bv, a3.y+bv);
    }
}

// ---------------------------------------------------------------------------
// Row-window loader: 3 rows x (XPT+2) window around (y, tx*XPT) built from
// predicated vector loads + warp shuffles for the +/-1 halo. Sync-free.
// ---------------------------------------------------------------------------
template<int XPT>
__device__ __forceinline__ void load_win3(
    const float* __restrict__ Xc, int y, int Hi, int Wi, int tx,
    float win[3][XPT + 2])
{
#pragma unroll
    for (int r = 0; r < 3; r++) {
        int gy = y - 1 + r;
        bool ok = (unsigned)gy < (unsigned)Hi;
        if (XPT == 4) {
            float4 v = make_float4(0.f, 0.f, 0.f, 0.f);
            if (ok) v = *(const float4*)(Xc + gy * Wi + tx * 4);
            float lw = __shfl_up_sync(0xffffffffu, v.w, 1);
            float rw = __shfl_down_sync(0xffffffffu, v.x, 1);
            win[r][0] = (tx == 0) ? 0.f : lw;
            win[r][1] = v.x; win[r][2] = v.y; win[r][3] = v.z; win[r][4] = v.w;
            win[r][5] = (tx == 31) ? 0.f : rw;
        } else {
            float2 v = make_float2(0.f, 0.f);
            if (ok) v = *(const float2*)(Xc + gy * Wi + tx * 2);
            float lw = __shfl_up_sync(0xffffffffu, v.y, 1);
            float rw = __shfl_down_sync(0xffffffffu, v.x, 1);
            win[r][0] = (tx == 0) ? 0.f : lw;
            win[r][1] = v.x; win[r][2] = v.y;
            win[r][3] = (tx == 31) ? 0.f : rw;
        }
    }
}

// ---------------------------------------------------------------------------
// conv3x3, pad=1, Cin=64, FFMA2 inner math. Weights preloaded once (single
// barrier); mainloop sync-free. blockDim(32,4); XPT px per thread.
// NP = XPT/2 packed accumulators per output channel.
// ---------------------------------------------------------------------------
template<int K2C, int K2, int XPT>
__global__ void __launch_bounds__(128) conv3x3_kernel(
    const float* __restrict__ X, const float* __restrict__ Wt,
    const float* __restrict__ Bi, float* __restrict__ Y,
    int Hi, int Wi)
{
    constexpr int NP = XPT / 2;
    const int n   = blockIdx.z;
    const int oc0 = blockIdx.x * K2C;
    const int y0  = blockIdx.y * 4;
    const int tx = threadIdx.x, ty = threadIdx.y;
    const int tid = ty * 32 + tx;
    const int y = y0 + ty;

    __shared__ float ws[CCC * K2C * 9];
    for (int i = tid; i < CCC * K2C * 9; i += 128) {
        int c = i / (K2C * 9);
        int r = i % (K2C * 9);
        int o = r / 9, k = r % 9;
        ws[i] = Wt[((oc0 + o) * CCC + c) * 9 + k];
    }
    __syncthreads();   // only barrier in the kernel

    u64x acc2[K2C][NP];
#pragma unroll
    for (int o = 0; o < K2C; o++)
#pragma unroll
        for (int j = 0; j < NP; j++) acc2[o][j] = 0ULL;

    const int HWi = Hi * Wi;
    const float* Xn = X + (size_t)n * CCC * HWi;

#pragma unroll 2
    for (int c = 0; c < CCC; c++) {
        float win[3][XPT + 2];
        load_win3<XPT>(Xn + (size_t)c * HWi, y, Hi, Wi, tx, win);

        u64x wp[3][XPT + 1];
#pragma unroll
        for (int r = 0; r < 3; r++)
#pragma unroll
            for (int m = 0; m < XPT + 1; m++)
                wp[r][m] = pk2(win[r][m], win[r][m + 1]);

        const float* wc = &ws[c * K2C * 9];
#pragma unroll
        for (int o = 0; o < K2C; o++)
#pragma unroll
            for (int r = 0; r < 3; r++)
#pragma unroll
                for (int dc = 0; dc < 3; dc++) {
                    float w = wc[o * 9 + r * 3 + dc];
                    u64x w2 = pk2(w, w);
#pragma unroll
                    for (int j = 0; j < NP; j++)
                        acc2[o][j] = fma2(w2, wp[r][dc + 2 * j], acc2[o][j]);
                }
    }

#pragma unroll
    for (int o = 0; o < K2C; o++) {
        float bv = Bi[oc0 + o];
        size_t base = (((size_t)n * K2 + oc0 + o) * Hi + y) * Wi + tx * XPT;
#pragma unroll
        for (int j = 0; j < NP; j++) {
            float2 a = up2(acc2[o][j]);
            Y[base + 2*j]     = a.x + bv;
            Y[base + 2*j + 1] = a.y + bv;
        }
    }
}

// ---------------------------------------------------------------------------
// per-pixel softmax over K2 channel axis. Layout [n][K2][HWX].
// ---------------------------------------------------------------------------
template<int K2>
__global__ void softmax_kernel(const float* __restrict__ X, float* __restrict__ Y)
{
    const int p = blockIdx.x * 256 + threadIdx.x;
    const int n = blockIdx.z;
    const float* xp = X + (size_t)n * K2 * HWX + p;
    float v[K2];
    float mx = -1e30f;
#pragma unroll
    for (int j = 0; j < K2; j++) { v[j] = xp[(size_t)j * HWX]; mx = fmaxf(mx, v[j]); }
    float s = 0.f;
#pragma unroll
    for (int j = 0; j < K2; j++) { v[j] = __expf(v[j] - mx); s += v[j]; }
    float inv = 1.f / s;
    float* yp = Y + (size_t)n * K2 * HWX + p;
#pragma unroll
    for (int j = 0; j < K2; j++) yp[(size_t)j * HWX] = v[j] * inv;
}

// ---------------------------------------------------------------------------
// CARAFE scale=1, k=3, fused residual + INLINE softmax over 9 raw logits:
// Y = 2*F - sum_j softmax(m)[j]*window[j].
// Sync-free, smem-free; masks packed NEGATED once -> pure FFMA2 inner loop.
// ---------------------------------------------------------------------------
template<int CCH>
__global__ void __launch_bounds__(128) carafe_s1_kernel(
    const float* __restrict__ F, const float* __restrict__ M,
    float* __restrict__ Y, int C)
{
    const int n  = blockIdx.z;
    const int y0 = blockIdx.y * 4;
    const int c0 = blockIdx.x * CCH;
    const int tx = threadIdx.x, ty = threadIdx.y;
    const int y  = y0 + ty;
    const int xb = tx * 4;

    float mk[9][4];
    const float* Mn = M + (size_t)n * 9 * HWX;
#pragma unroll
    for (int j = 0; j < 9; j++) {
        float4 m4 = *(const float4*)&Mn[(size_t)j * HWX + y * WW + xb];
        mk[j][0] = m4.x; mk[j][1] = m4.y; mk[j][2] = m4.z; mk[j][3] = m4.w;
    }
#pragma unroll
    for (int px = 0; px < 4; px++) {
        float mx = mk[0][px];
#pragma unroll
        for (int j = 1; j < 9; j++) mx = fmaxf(mx, mk[j][px]);
        float s = 0.f;
#pragma unroll
        for (int j = 0; j < 9; j++) { mk[j][px] = __expf(mk[j][px] - mx); s += mk[j][px]; }
        float inv = -1.f / s;                 // NEGATED for fma-subtract
#pragma unroll
        for (int j = 0; j < 9; j++) mk[j][px] *= inv;
    }
    u64x mk2[9][2];
#pragma unroll
    for (int j = 0; j < 9; j++) {
        mk2[j][0] = pk2(mk[j][0], mk[j][1]);
        mk2[j][1] = pk2(mk[j][2], mk[j][3]);
    }

    const float* Fn = F + (size_t)n * C * HWX;
    float* Yn = Y + (size_t)n * C * HWX;

#pragma unroll 2
    for (int cc = 0; cc < CCH; cc++) {
        const int c = c0 + cc;
        float win[3][6];
        load_win3<4>(Fn + (size_t)c * HWX, y, HH, WW, tx, win);

        u64x wp[3][5];
#pragma unroll
        for (int r = 0; r < 3; r++)
#pragma unroll
            for (int m = 0; m < 5; m++)
                wp[r][m] = pk2(win[r][m], win[r][m + 1]);

        u64x o2[2];
        o2[0] = pk2(2.f * win[1][1], 2.f * win[1][2]);
        o2[1] = pk2(2.f * win[1][3], 2.f * win[1][4]);
#pragma unroll
        for (int r = 0; r < 3; r++)
#pragma unroll
            for (int dc = 0; dc < 3; dc++) {
                o2[0] = fma2(mk2[r * 3 + dc][0], wp[r][dc],     o2[0]);
                o2[1] = fma2(mk2[r * 3 + dc][1], wp[r][dc + 2], o2[1]);
            }

        float2 a = up2(o2[0]), b = up2(o2[1]);
        *(float4*)&Yn[(size_t)c * HWX + y * WW + xb] =
            make_float4(a.x, a.y, b.x, b.y);
    }
}

// ---------------------------------------------------------------------------
// CARAFE scale=2, k=5. F:[n][C][64][64], M:[n][25][128][128].
// ALL channel tiles of the chunk preloaded to smem -> ONE __syncthreads,
// then sync-free channel loop.
// ---------------------------------------------------------------------------
template<bool ADD, bool SMAX, int CC>
__global__ void __launch_bounds__(256) carafe_s2_kernel(
    const float* __restrict__ F, const float* __restrict__ M,
    const float* __restrict__ B, float* __restrict__ Y, int C)
{
    const int n  = blockIdx.z;
    const int xt = blockIdx.x & 1;
    const int c0 = (blockIdx.x >> 1) * CC;
    const int x0 = xt * 64, y0 = blockIdx.y * 8;
    const int tx = threadIdx.x, ty = threadIdx.y;
    const int tid = ty * 32 + tx;
    const int xo = x0 + tx * 2;
    const int yo = y0 + ty;

    __shared__ float tile[CC][8][36];

    float mk0[25], mk1[25];
    const float* Mn = M + (size_t)n * 25 * HWX;
#pragma unroll
    for (int j = 0; j < 25; j++) {
        float2 m2 = *(const float2*)&Mn[(size_t)j * HWX + yo * WW + xo];
        mk0[j] = m2.x; mk1[j] = m2.y;
    }
    if (SMAX) {
        float mx0 = mk0[0], mx1 = mk1[0];
#pragma unroll
        for (int j = 1; j < 25; j++) { mx0 = fmaxf(mx0, mk0[j]); mx1 = fmaxf(mx1, mk1[j]); }
        float s0 = 0.f, s1 = 0.f;
#pragma unroll
        for (int j = 0; j < 25; j++) {
            mk0[j] = __expf(mk0[j] - mx0); s0 += mk0[j];
            mk1[j] = __expf(mk1[j] - mx1); s1 += mk1[j];
        }
        float i0 = 1.f / s0, i1 = 1.f / s1;
#pragma unroll
        for (int j = 0; j < 25; j++) { mk0[j] *= i0; mk1[j] *= i1; }
    }

    const int ylb = y0 / 2 - 2, xlb = x0 / 2 - 2;
    const int rb  = ty >> 1;
    const float* Fn = F + (size_t)n * C * HW2;
    const int cend = (c0 + CC < C) ? c0 + CC : C;
    const int nch  = cend - c0;

    // preload all channel tiles (one barrier total)
    for (int i = tid; i < nch * 288; i += 256) {
        int cc = i / 288, rem = i % 288;
        int r = rem / 36, col = rem % 36;
        int gy = ylb + r, gx = xlb + col;
        float v = 0.f;
        if ((unsigned)gy < H2 && (unsigned)gx < W2)
            v = Fn[(size_t)(c0 + cc) * HW2 + gy * W2 + gx];
        tile[cc][r][col] = v;
    }
    __syncthreads();

#pragma unroll 2
    for (int cc = 0; cc < nch; cc++) {
        float a0 = 0.f, a1 = 0.f;
#pragma unroll
        for (int ki = 0; ki < 5; ki++)
#pragma unroll
            for (int kj = 0; kj < 5; kj++) {
                float v = tile[cc][rb + ki][tx + kj];
                a0 += v * mk0[ki * 5 + kj];
                a1 += v * mk1[ki * 5 + kj];
            }

        size_t oidx = (((size_t)n * C + c0 + cc) * HH + yo) * WW + xo;
        if (ADD) {
            float2 b2 = *(const float2*)&B[oidx];
            a0 += b2.x; a1 += b2.y;
        }
        *(float2*)&Y[oidx] = make_float2(a0, a1);
    }
}

// ---------------------------------------------------------------------------
// Orchestration (graph-capturable: kernel launches only)
// ---------------------------------------------------------------------------
extern "C" void kernel_launch(void* const* d_in, const int* in_sizes, int n_in,
                              void* d_out, int out_size)
{
    const float* hr_feat = (const float*)d_in[0];
    const float* lr_feat = (const float*)d_in[1];
    const float* hr_w    = (const float*)d_in[2];
    const float* hr_b    = (const float*)d_in[3];
    const float* lr_w    = (const float*)d_in[4];
    const float* lr_b    = (const float*)d_in[5];
    const float* enc_w   = (const float*)d_in[6];
    const float* enc_b   = (const float*)d_in[7];
    const float* enc2_w  = (const float*)d_in[8];
    const float* enc2_b  = (const float*)d_in[9];
    float* out = (float*)d_out;

    float *p_chf, *p_chf2, *p_clf, *p_mhh, *p_mlh, *p_mlh2, *p_mlll, *p_e2clf;
    cudaGetSymbolAddress((void**)&p_chf,   g_chf);
    cudaGetSymbolAddress((void**)&p_chf2,  g_chf2);
    cudaGetSymbolAddress((void**)&p_clf,   g_clf);
    cudaGetSymbolAddress((void**)&p_mhh,   g_mhh);
    cudaGetSymbolAddress((void**)&p_mlh,   g_mlh);
    cudaGetSymbolAddress((void**)&p_mlh2,  g_mlh2);
    cudaGetSymbolAddress((void**)&p_mlll,  g_mlll);
    cudaGetSymbolAddress((void**)&p_e2clf, g_e2clf);

    const size_t MASK_SZ = (size_t)NB * 25 * HWX;
    const size_t FEAT_SZ = (size_t)NB * 256 * HWX;
    float* out_mask = out;                          // mask_lr_out
    float* out_hr   = out + MASK_SZ;                // hr_out
    float* out_lr   = out + MASK_SZ + FEAT_SZ;      // lr_out

    dim3 bm(32, 4), bm2(32, 8);

    // chf = conv1x1(hr_feat), clf = conv1x1(lr_feat)
    conv1x1_kernel<<<dim3(HWX/256, 1, NB), 256>>>(hr_feat, hr_w, hr_b, p_chf, HWX);
    conv1x1_kernel<<<dim3(HW2/256, 1, NB), 256>>>(lr_feat, lr_w, lr_b, p_clf, HW2);

    // mask_hr_hr = enc2(chf)
    conv3x3_kernel<3, 9, 4><<<dim3(3, HH/4, NB), bm>>>(p_chf, enc2_w, enc2_b, p_mhh, HH, WW);

    // chf' = 2*chf - carafe(chf, softmax9(mask_hr_hr), 3, 1)   (softmax inlined)
    carafe_s1_kernel<8><<<dim3(CCC/8, HH/4, NB), bm>>>(p_chf, p_mhh, p_chf2, CCC);

    // mask_lr_hr = enc(chf'); mask_lr_lr_lr = enc(clf)
    conv3x3_kernel<5, 25, 4><<<dim3(5, HH/4, NB), bm>>>(p_chf2, enc_w, enc_b, p_mlh, HH, WW);
    conv3x3_kernel<5, 25, 2><<<dim3(5, H2/4, NB), bm>>>(p_clf, enc_w, enc_b, p_mlll, H2, W2);

    // mask_lr = mask_lr_hr + carafe(mask_lr_lr_lr, softmax25(mask_lr_hr), 5, 2)
    carafe_s2_kernel<true, true, 4><<<dim3(2 * 7, HH/8, NB), bm2>>>(p_mlll, p_mlh, p_mlh, p_mlh2, 25);

    // mask_lr_out = softmax25(mask_lr) -> output 0 (also operand of last carafes)
    softmax_kernel<25><<<dim3(HWX/256, 1, NB), 256>>>(p_mlh2, out_mask);

    // mask_hr = mask_hr_hr + carafe(enc2(clf), mask_lr_out, 5, 2)
    conv3x3_kernel<3, 9, 2><<<dim3(3, H2/4, NB), bm>>>(p_clf, enc2_w, enc2_b, p_e2clf, H2, W2);
    carafe_s2_kernel<true, false, 2><<<dim3(2 * 5, HH/8, NB), bm2>>>(p_e2clf, out_mask, p_mhh, p_mhh, 9);

    // hr_out = 2*hr_feat - carafe(hr_feat, softmax9(mask_hr), 3, 1) -> output 1
    carafe_s1_kernel<8><<<dim3(256/8, HH/4, NB), bm>>>(hr_feat, p_mhh, out_hr, 256);

    // lr_out = carafe(lr_feat, mask_lr_out, 5, 2) -> output 2
    carafe_s2_kernel<false, false, 16><<<dim3(2 * 16, HH/8, NB), bm2>>>(lr_feat, out_mask, nullptr, out_lr, 256);
}

// round 17
// speedup vs baseline: 4.2469x; 1.1143x over previous
#include <cuda_runtime.h>

// ---------------------------------------------------------------------------
// Problem constants (fixed shapes from setup_inputs)
// ---------------------------------------------------------------------------
#define NB   4
#define CIN  256          // CH == CL == 256
#define CCC  64           // compressed channels
#define HH   128
#define WW   128
#define HWX  (HH*WW)      // 16384
#define H2   64
#define W2   64
#define HW2  (H2*W2)      // 4096

typedef unsigned long long u64x;

// packed fp32x2 helpers (Blackwell FFMA2 path — only reachable via PTX)
__device__ __forceinline__ u64x pk2(float lo, float hi) {
    u64x r; asm("mov.b64 %0, {%1, %2};" : "=l"(r) : "f"(lo), "f"(hi)); return r;
}
__device__ __forceinline__ float2 up2(u64x v) {
    float2 f; asm("mov.b64 {%0, %1}, %2;" : "=f"(f.x), "=f"(f.y) : "l"(v)); return f;
}
__device__ __forceinline__ u64x fma2(u64x a, u64x b, u64x c) {
    u64x d; asm("fma.rn.f32x2 %0, %1, %2, %3;" : "=l"(d) : "l"(a), "l"(b), "l"(c)); return d;
}

// ---------------------------------------------------------------------------
// Device-global scratch (no cudaMalloc allowed)
// ---------------------------------------------------------------------------
__device__ float g_chf  [NB*CCC*HWX];   // 16 MB
__device__ float g_chf2 [NB*CCC*HWX];   // 16 MB
__device__ float g_clf  [NB*CCC*HW2];   // 4 MB
__device__ float g_mhh  [NB*9 *HWX];    // mask_hr_hr -> mask_hr (in-place add)
__device__ float g_mlh  [NB*25*HWX];    // mask_lr_hr (raw logits)
__device__ float g_mlll [NB*25*HW2];    // enc(clf)
__device__ float g_e2clf[NB*9 *HW2];    // enc2(clf)

// ---------------------------------------------------------------------------
// conv1x1 as SGEMM: Y[n][oc][p] = b[oc] + sum_c W[oc][c] * X[n][c][p]
// M=64, K=256; BN=256 pixels, BK=16; thread tile 8 oc x 8 px.
// Double-buffered smem (1 barrier per K-chunk) + FFMA2 inner product.
// ---------------------------------------------------------------------------
__global__ void __launch_bounds__(256) conv1x1_kernel(
    const float* __restrict__ X, const float* __restrict__ Wt,
    const float* __restrict__ Bi, float* __restrict__ Y, int P)
{
    __shared__ float Ws[2][16][64];
    __shared__ float Xs[2][16][256];
    const int n  = blockIdx.z;
    const int p0 = blockIdx.x * 256;
    const int tid = threadIdx.x;
    const int tx = tid & 31;   // pixel group (8 px each)
    const int ty = tid >> 5;   // oc group (8 oc each)
    const float* Xn = X + (size_t)n * CIN * P;

    const int wk = tid >> 6, wm = tid & 63;
    const int xk = tid >> 6;
    const int xp = (tid & 63) << 2;

    u64x acc2[8][4];
#pragma unroll
    for (int i = 0; i < 8; i++)
#pragma unroll
        for (int j = 0; j < 4; j++) acc2[i][j] = 0ULL;

#pragma unroll
    for (int i = 0; i < 4; i++)
        Ws[0][wk + i * 4][wm] = Wt[wm * CIN + wk + i * 4];
#pragma unroll
    for (int i = 0; i < 4; i++)
        *(float4*)&Xs[0][xk + i * 4][xp] =
            *(const float4*)&Xn[(size_t)(xk + i * 4) * P + p0 + xp];
    __syncthreads();

#pragma unroll 1
    for (int k0 = 0; k0 < 16; k0++) {
        const int buf = k0 & 1;
        float  wpre[4];
        float4 xpre[4];
        if (k0 < 15) {
            int kb = (k0 + 1) * 16;
#pragma unroll
            for (int i = 0; i < 4; i++)
                wpre[i] = Wt[wm * CIN + kb + wk + i * 4];
#pragma unroll
            for (int i = 0; i < 4; i++)
                xpre[i] = *(const float4*)&Xn[(size_t)(kb + xk + i * 4) * P + p0 + xp];
        }

#pragma unroll
        for (int k = 0; k < 16; k++) {
            float rw[8], rx[8];
            *(float4*)&rw[0] = *(float4*)&Ws[buf][k][ty * 8];
            *(float4*)&rw[4] = *(float4*)&Ws[buf][k][ty * 8 + 4];
            *(float4*)&rx[0] = *(float4*)&Xs[buf][k][tx * 8];
            *(float4*)&rx[4] = *(float4*)&Xs[buf][k][tx * 8 + 4];
            u64x x2[4];
#pragma unroll
            for (int j = 0; j < 4; j++) x2[j] = pk2(rx[2*j], rx[2*j+1]);
#pragma unroll
            for (int i = 0; i < 8; i++) {
                u64x w2 = pk2(rw[i], rw[i]);
#pragma unroll
                for (int j = 0; j < 4; j++)
                    acc2[i][j] = fma2(w2, x2[j], acc2[i][j]);
            }
        }

        if (k0 < 15) {
            const int nb = buf ^ 1;
#pragma unroll
            for (int i = 0; i < 4; i++) Ws[nb][wk + i * 4][wm] = wpre[i];
#pragma unroll
            for (int i = 0; i < 4; i++) *(float4*)&Xs[nb][xk + i * 4][xp] = xpre[i];
        }
        __syncthreads();
    }

#pragma unroll
    for (int i = 0; i < 8; i++) {
        int oc = ty * 8 + i;
        float bv = Bi[oc];
        size_t base = ((size_t)n * CCC + oc) * P + p0 + tx * 8;
        float2 a0 = up2(acc2[i][0]), a1 = up2(acc2[i][1]);
        float2 a2 = up2(acc2[i][2]), a3 = up2(acc2[i][3]);
        *(float4*)&Y[base]     = make_float4(a0.x+bv, a0.y+bv, a1.x+bv, a1.y+bv);
        *(float4*)&Y[base + 4] = make_float4(a2.x+bv, a2.y+bv, a3.x+bv, a3.y+bv);
    }
}

// ---------------------------------------------------------------------------
// Direct-load 3-row window: vector body + 2 scalar halo loads per row.
// 9 independent LDGs (MLP=9), NO shuffles, sync-free.
// ---------------------------------------------------------------------------
template<int XPT>
struct Rows { float v[3][XPT]; float lo[3]; float hi[3]; };

template<int XPT>
__device__ __forceinline__ Rows<XPT> load_rows(
    const float* __restrict__ Xc, int y, int Hi, int Wi, int xb)
{
    Rows<XPT> R;
#pragma unroll
    for (int r = 0; r < 3; r++) {
        int gy = y - 1 + r;
        bool ok = (unsigned)gy < (unsigned)Hi;
        const float* row = Xc + gy * Wi;
        if (XPT == 4) {
            float4 t = make_float4(0.f, 0.f, 0.f, 0.f);
            if (ok) t = *(const float4*)(row + xb);
            R.v[r][0] = t.x; R.v[r][1] = t.y; R.v[r][2] = t.z; R.v[r][3] = t.w;
        } else {
            float2 t = make_float2(0.f, 0.f);
            if (ok) t = *(const float2*)(row + xb);
            R.v[r][0] = t.x; R.v[r][1] = t.y;
        }
        R.lo[r] = (ok && xb > 0)        ? row[xb - 1]   : 0.f;
        R.hi[r] = (ok && xb + XPT < Wi) ? row[xb + XPT] : 0.f;
    }
    return R;
}

template<int XPT>
__device__ __forceinline__ void rows_to_win(const Rows<XPT>& R, float win[3][XPT + 2])
{
#pragma unroll
    for (int r = 0; r < 3; r++) {
        win[r][0] = R.lo[r];
#pragma unroll
        for (int j = 0; j < XPT; j++) win[r][j + 1] = R.v[r][j];
        win[r][XPT + 1] = R.hi[r];
    }
}

// ---------------------------------------------------------------------------
// conv3x3, pad=1, Cin=64, FFMA2 math. Weights preloaded once (single
// barrier); channel loop SOFTWARE-PIPELINED (prefetch c+1 while computing c).
// blockDim(32,4); XPT px per thread.
// ---------------------------------------------------------------------------
template<int K2C, int K2, int XPT>
__global__ void __launch_bounds__(128) conv3x3_kernel(
    const float* __restrict__ X, const float* __restrict__ Wt,
    const float* __restrict__ Bi, float* __restrict__ Y,
    int Hi, int Wi)
{
    constexpr int NP = XPT / 2;
    const int n   = blockIdx.z;
    const int oc0 = blockIdx.x * K2C;
    const int y0  = blockIdx.y * 4;
    const int tx = threadIdx.x, ty = threadIdx.y;
    const int tid = ty * 32 + tx;
    const int y  = y0 + ty;
    const int xb = tx * XPT;

    __shared__ float ws[CCC * K2C * 9];
    for (int i = tid; i < CCC * K2C * 9; i += 128) {
        int c = i / (K2C * 9);
        int r = i % (K2C * 9);
        int o = r / 9, k = r % 9;
        ws[i] = Wt[((oc0 + o) * CCC + c) * 9 + k];
    }
    __syncthreads();   // only barrier in the kernel

    u64x acc2[K2C][NP];
#pragma unroll
    for (int o = 0; o < K2C; o++)
#pragma unroll
        for (int j = 0; j < NP; j++) acc2[o][j] = 0ULL;

    const int HWi = Hi * Wi;
    const float* Xn = X + (size_t)n * CCC * HWi;

    const float* Xc = Xn;
    Rows<XPT> cur = load_rows<XPT>(Xc, y, Hi, Wi, xb);

#pragma unroll 2
    for (int c = 0; c < CCC; c++) {
        const float* Xc1 = Xc + HWi;
        Rows<XPT> nxt = load_rows<XPT>((c + 1 < CCC) ? Xc1 : Xc, y, Hi, Wi, xb);

        float win[3][XPT + 2];
        rows_to_win<XPT>(cur, win);

        u64x wp[3][XPT + 1];
#pragma unroll
        for (int r = 0; r < 3; r++)
#pragma unroll
            for (int m = 0; m < XPT + 1; m++)
                wp[r][m] = pk2(win[r][m], win[r][m + 1]);

        const float* wc = &ws[c * K2C * 9];
#pragma unroll
        for (int o = 0; o < K2C; o++)
#pragma unroll
            for (int r = 0; r < 3; r++)
#pragma unroll
                for (int dc = 0; dc < 3; dc++) {
                    float w = wc[o * 9 + r * 3 + dc];
                    u64x w2 = pk2(w, w);
#pragma unroll
                    for (int j = 0; j < NP; j++)
                        acc2[o][j] = fma2(w2, wp[r][dc + 2 * j], acc2[o][j]);
                }

        cur = nxt;
        Xc  = Xc1;
    }

#pragma unroll
    for (int o = 0; o < K2C; o++) {
        float bv = Bi[oc0 + o];
        size_t base = (((size_t)n * K2 + oc0 + o) * Hi + y) * Wi + xb;
#pragma unroll
        for (int j = 0; j < NP; j++) {
            float2 a = up2(acc2[o][j]);
            Y[base + 2*j]     = a.x + bv;
            Y[base + 2*j + 1] = a.y + bv;
        }
    }
}

// ---------------------------------------------------------------------------
// CARAFE scale=1, k=3, fused residual + INLINE softmax over 9 raw logits:
// Y = 2*F - sum_j softmax(m)[j]*window[j].
// Sync-free, smem-free, software-pipelined channel loop, FFMA2 math.
// ---------------------------------------------------------------------------
template<int CCH>
__global__ void __launch_bounds__(128) carafe_s1_kernel(
    const float* __restrict__ F, const float* __restrict__ M,
    float* __restrict__ Y, int C)
{
    const int n  = blockIdx.z;
    const int y0 = blockIdx.y * 4;
    const int c0 = blockIdx.x * CCH;
    const int tx = threadIdx.x, ty = threadIdx.y;
    const int y  = y0 + ty;
    const int xb = tx * 4;

    float mk[9][4];
    const float* Mn = M + (size_t)n * 9 * HWX;
#pragma unroll
    for (int j = 0; j < 9; j++) {
        float4 m4 = *(const float4*)&Mn[(size_t)j * HWX + y * WW + xb];
        mk[j][0] = m4.x; mk[j][1] = m4.y; mk[j][2] = m4.z; mk[j][3] = m4.w;
    }
#pragma unroll
    for (int px = 0; px < 4; px++) {
        float mx = mk[0][px];
#pragma unroll
        for (int j = 1; j < 9; j++) mx = fmaxf(mx, mk[j][px]);
        float s = 0.f;
#pragma unroll
        for (int j = 0; j < 9; j++) { mk[j][px] = __expf(mk[j][px] - mx); s += mk[j][px]; }
        float inv = -1.f / s;                 // NEGATED for fma-subtract
#pragma unroll
        for (int j = 0; j < 9; j++) mk[j][px] *= inv;
    }
    u64x mk2[9][2];
#pragma unroll
    for (int j = 0; j < 9; j++) {
        mk2[j][0] = pk2(mk[j][0], mk[j][1]);
        mk2[j][1] = pk2(mk[j][2], mk[j][3]);
    }

    const float* Fn = F + (size_t)n * C * HWX;
    float* Yn = Y + (size_t)n * C * HWX;

    const float* Fc = Fn + (size_t)c0 * HWX;
    Rows<4> cur = load_rows<4>(Fc, y, HH, WW, xb);

#pragma unroll 2
    for (int cc = 0; cc < CCH; cc++) {
        const float* Fc1 = Fc + HWX;
        Rows<4> nxt = load_rows<4>((cc + 1 < CCH) ? Fc1 : Fc, y, HH, WW, xb);

        float win[3][6];
        rows_to_win<4>(cur, win);

        u64x wp[3][5];
#pragma unroll
        for (int r = 0; r < 3; r++)
#pragma unroll
            for (int m = 0; m < 5; m++)
                wp[r][m] = pk2(win[r][m], win[r][m + 1]);

        u64x o2[2];
        o2[0] = pk2(2.f * win[1][1], 2.f * win[1][2]);
        o2[1] = pk2(2.f * win[1][3], 2.f * win[1][4]);
#pragma unroll
        for (int r = 0; r < 3; r++)
#pragma unroll
            for (int dc = 0; dc < 3; dc++) {
                o2[0] = fma2(mk2[r * 3 + dc][0], wp[r][dc],     o2[0]);
                o2[1] = fma2(mk2[r * 3 + dc][1], wp[r][dc + 2], o2[1]);
            }

        float2 a = up2(o2[0]), b = up2(o2[1]);
        *(float4*)&Yn[(size_t)(c0 + cc) * HWX + y * WW + xb] =
            make_float4(a.x, a.y, b.x, b.y);

        cur = nxt;
        Fc  = Fc1;
    }
}

// ---------------------------------------------------------------------------
// FUSED mask_lr pipeline (G+H): per output pixel,
//   l[25]  = mask_lr_hr logits
//   m      = softmax25(l)
//   out[j] = l[j] + carafe_j(mlll, m)     (scale=2, k=5)
//   write softmax25(out)  -> out_mask  (== mask_lr_init == mask_lr_out)
// Each thread owns 2 x-pixels sharing one 5x5 low-res window; all 25 feature
// channels in smem (one barrier). Grid (2, 32, NB), block (32,4).
// ---------------------------------------------------------------------------
__global__ void __launch_bounds__(128) carafe_mask25_kernel(
    const float* __restrict__ F,   // mlll [n][25][64][64]
    const float* __restrict__ L,   // mask_lr_hr raw [n][25][128][128]
    float* __restrict__ Y)         // out_mask [n][25][128][128]
{
    const int n  = blockIdx.z;
    const int x0 = blockIdx.x * 64;
    const int y0 = blockIdx.y * 4;
    const int tx = threadIdx.x, ty = threadIdx.y;
    const int tid = ty * 32 + tx;
    const int xo = x0 + tx * 2;
    const int yo = y0 + ty;

    __shared__ float tile[25][6][36];

    float l0[25], l1[25];
    const float* Ln = L + (size_t)n * 25 * HWX;
#pragma unroll
    for (int j = 0; j < 25; j++) {
        float2 t = *(const float2*)&Ln[(size_t)j * HWX + yo * WW + xo];
        l0[j] = t.x; l1[j] = t.y;
    }

    // softmax of raw logits -> masks m (keep l as the additive base)
    float m0[25], m1[25];
    {
        float mx0 = l0[0], mx1 = l1[0];
#pragma unroll
        for (int j = 1; j < 25; j++) { mx0 = fmaxf(mx0, l0[j]); mx1 = fmaxf(mx1, l1[j]); }
        float s0 = 0.f, s1 = 0.f;
#pragma unroll
        for (int j = 0; j < 25; j++) {
            m0[j] = __expf(l0[j] - mx0); s0 += m0[j];
            m1[j] = __expf(l1[j] - mx1); s1 += m1[j];
        }
        float i0 = 1.f / s0, i1 = 1.f / s1;
#pragma unroll
        for (int j = 0; j < 25; j++) { m0[j] *= i0; m1[j] *= i1; }
    }

    // load all 25 channel tiles (6 rows x 36 cols) — single barrier
    const int ylb = y0 / 2 - 2, xlb = x0 / 2 - 2;
    const float* Fn = F + (size_t)n * 25 * HW2;
    for (int i = tid; i < 25 * 216; i += 128) {
        int j = i / 216, rem = i % 216;
        int r = rem / 36, col = rem % 36;
        int gy = ylb + r, gx = xlb + col;
        float v = 0.f;
        if ((unsigned)gy < H2 && (unsigned)gx < W2)
            v = Fn[(size_t)j * HW2 + gy * W2 + gx];
        tile[j][r][col] = v;
    }
    __syncthreads();

    const int rb = ty >> 1;
#pragma unroll 1
    for (int j = 0; j < 25; j++) {
        float a0 = l0[j], a1 = l1[j];
#pragma unroll
        for (int ki = 0; ki < 5; ki++)
#pragma unroll
            for (int kj = 0; kj < 5; kj++) {
                float v = tile[j][rb + ki][tx + kj];
                a0 += v * m0[ki * 5 + kj];
                a1 += v * m1[ki * 5 + kj];
            }
        l0[j] = a0; l1[j] = a1;
    }

    // final softmax over channel axis, write out_mask
    {
        float mx0 = l0[0], mx1 = l1[0];
#pragma unroll
        for (int j = 1; j < 25; j++) { mx0 = fmaxf(mx0, l0[j]); mx1 = fmaxf(mx1, l1[j]); }
        float s0 = 0.f, s1 = 0.f;
#pragma unroll
        for (int j = 0; j < 25; j++) {
            l0[j] = __expf(l0[j] - mx0); s0 += l0[j];
            l1[j] = __expf(l1[j] - mx1); s1 += l1[j];
        }
        float i0 = 1.f / s0, i1 = 1.f / s1;
        float* Yp = Y + (size_t)n * 25 * HWX + yo * WW + xo;
#pragma unroll
        for (int j = 0; j < 25; j++)
            *(float2*)&Yp[(size_t)j * HWX] = make_float2(l0[j] * i0, l1[j] * i1);
    }
}

// ---------------------------------------------------------------------------
// CARAFE scale=2, k=5. F:[n][C][64][64], M normalized:[n][25][128][128].
// ALL channel tiles of the chunk preloaded to smem -> ONE __syncthreads,
// then sync-free channel loop. ADD: Y = B + carafe (in-place safe).
// ---------------------------------------------------------------------------
template<bool ADD, int CC>
__global__ void __launch_bounds__(256) carafe_s2_kernel(
    const float* __restrict__ F, const float* __restrict__ M,
    const float* __restrict__ B, float* __restrict__ Y, int C)
{
    const int n  = blockIdx.z;
    const int xt = blockIdx.x & 1;
    const int c0 = (blockIdx.x >> 1) * CC;
    const int x0 = xt * 64, y0 = blockIdx.y * 8;
    const int tx = threadIdx.x, ty = threadIdx.y;
    const int tid = ty * 32 + tx;
    const int xo = x0 + tx * 2;
    const int yo = y0 + ty;

    __shared__ float tile[CC][8][36];

    float mk0[25], mk1[25];
    const float* Mn = M + (size_t)n * 25 * HWX;
#pragma unroll
    for (int j = 0; j < 25; j++) {
        float2 m2 = *(const float2*)&Mn[(size_t)j * HWX + yo * WW + xo];
        mk0[j] = m2.x; mk1[j] = m2.y;
    }

    const int ylb = y0 / 2 - 2, xlb = x0 / 2 - 2;
    const int rb  = ty >> 1;
    const float* Fn = F + (size_t)n * C * HW2;
    const int cend = (c0 + CC < C) ? c0 + CC : C;
    const int nch  = cend - c0;

    for (int i = tid; i < nch * 288; i += 256) {
        int cc = i / 288, rem = i % 288;
        int r = rem / 36, col = rem % 36;
        int gy = ylb + r, gx = xlb + col;
        float v = 0.f;
        if ((unsigned)gy < H2 && (unsigned)gx < W2)
            v = Fn[(size_t)(c0 + cc) * HW2 + gy * W2 + gx];
        tile[cc][r][col] = v;
    }
    __syncthreads();

#pragma unroll 2
    for (int cc = 0; cc < nch; cc++) {
        float a0 = 0.f, a1 = 0.f;
#pragma unroll
        for (int ki = 0; ki < 5; ki++)
#pragma unroll
            for (int kj = 0; kj < 5; kj++) {
                float v = tile[cc][rb + ki][tx + kj];
                a0 += v * mk0[ki * 5 + kj];
                a1 += v * mk1[ki * 5 + kj];
            }

        size_t oidx = (((size_t)n * C + c0 + cc) * HH + yo) * WW + xo;
        if (ADD) {
            float2 b2 = *(const float2*)&B[oidx];
            a0 += b2.x; a1 += b2.y;
        }
        *(float2*)&Y[oidx] = make_float2(a0, a1);
    }
}

// ---------------------------------------------------------------------------
// Orchestration: two-stream fork/join (graph-capturable via event deps).
//   stream 0 (critical): A -> C -> D -> E -> [wait side] G+H -> J -> K
//   stream s1 (side)   : B -> F -> I -> (eSide) ... (wait eMask) L -> (eL)
// ---------------------------------------------------------------------------
extern "C" void kernel_launch(void* const* d_in, const int* in_sizes, int n_in,
                              void* d_out, int out_size)
{
    const float* hr_feat = (const float*)d_in[0];
    const float* lr_feat = (const float*)d_in[1];
    const float* hr_w    = (const float*)d_in[2];
    const float* hr_b    = (const float*)d_in[3];
    const float* lr_w    = (const float*)d_in[4];
    const float* lr_b    = (const float*)d_in[5];
    const float* enc_w   = (const float*)d_in[6];
    const float* enc_b   = (const float*)d_in[7];
    const float* enc2_w  = (const float*)d_in[8];
    const float* enc2_b  = (const float*)d_in[9];
    float* out = (float*)d_out;

    float *p_chf, *p_chf2, *p_clf, *p_mhh, *p_mlh, *p_mlll, *p_e2clf;
    cudaGetSymbolAddress((void**)&p_chf,   g_chf);
    cudaGetSymbolAddress((void**)&p_chf2,  g_chf2);
    cudaGetSymbolAddress((void**)&p_clf,   g_clf);
    cudaGetSymbolAddress((void**)&p_mhh,   g_mhh);
    cudaGetSymbolAddress((void**)&p_mlh,   g_mlh);
    cudaGetSymbolAddress((void**)&p_mlll,  g_mlll);
    cudaGetSymbolAddress((void**)&p_e2clf, g_e2clf);

    const size_t MASK_SZ = (size_t)NB * 25 * HWX;
    const size_t FEAT_SZ = (size_t)NB * 256 * HWX;
    float* out_mask = out;                          // mask_lr_out
    float* out_hr   = out + MASK_SZ;                // hr_out
    float* out_lr   = out + MASK_SZ + FEAT_SZ;      // lr_out

    dim3 bm(32, 4), bm2(32, 8);
    cudaStream_t s0 = 0;

    // fork a side stream into the capture via event dependency
    cudaStream_t s1;
    cudaStreamCreateWithFlags(&s1, cudaStreamNonBlocking);
    cudaEvent_t eFork, eSide, eMask, eL;
    cudaEventCreateWithFlags(&eFork, cudaEventDisableTiming);
    cudaEventCreateWithFlags(&eSide, cudaEventDisableTiming);
    cudaEventCreateWithFlags(&eMask, cudaEventDisableTiming);
    cudaEventCreateWithFlags(&eL,    cudaEventDisableTiming);

    cudaEventRecord(eFork, s0);
    cudaStreamWaitEvent(s1, eFork, 0);

    // ---- side branch (clf chain) on s1 ----
    conv1x1_kernel<<<dim3(HW2/256, 1, NB), 256, 0, s1>>>(lr_feat, lr_w, lr_b, p_clf, HW2);
    conv3x3_kernel<5, 25, 2><<<dim3(5, H2/4, NB), bm, 0, s1>>>(p_clf, enc_w, enc_b, p_mlll, H2, W2);
    conv3x3_kernel<3, 9, 2><<<dim3(3, H2/4, NB), bm, 0, s1>>>(p_clf, enc2_w, enc2_b, p_e2clf, H2, W2);
    cudaEventRecord(eSide, s1);

    // ---- critical chain on stream 0 ----
    conv1x1_kernel<<<dim3(HWX/256, 1, NB), 256, 0, s0>>>(hr_feat, hr_w, hr_b, p_chf, HWX);
    conv3x3_kernel<3, 9, 4><<<dim3(3, HH/4, NB), bm, 0, s0>>>(p_chf, enc2_w, enc2_b, p_mhh, HH, WW);
    carafe_s1_kernel<8><<<dim3(CCC/8, HH/4, NB), bm, 0, s0>>>(p_chf, p_mhh, p_chf2, CCC);
    conv3x3_kernel<5, 25, 4><<<dim3(5, HH/4, NB), bm, 0, s0>>>(p_chf2, enc_w, enc_b, p_mlh, HH, WW);

    cudaStreamWaitEvent(s0, eSide, 0);
    // fused: mask_lr = mlh + carafe(mlll, softmax25(mlh)); out_mask = softmax25(mask_lr)
    carafe_mask25_kernel<<<dim3(2, HH/4, NB), bm, 0, s0>>>(p_mlll, p_mlh, out_mask);
    cudaEventRecord(eMask, s0);

    // ---- lr_out on side stream (independent of hr tail) ----
    cudaStreamWaitEvent(s1, eMask, 0);
    carafe_s2_kernel<false, 16><<<dim3(2 * 16, HH/8, NB), bm2, 0, s1>>>(lr_feat, out_mask, nullptr, out_lr, 256);
    cudaEventRecord(eL, s1);

    // ---- hr tail on stream 0 ----
    // mask_hr = mask_hr_hr + carafe(enc2(clf), out_mask, 5, 2)  (in-place add)
    carafe_s2_kernel<true, 2><<<dim3(2 * 5, HH/8, NB), bm2, 0, s0>>>(p_e2clf, out_mask, p_mhh, p_mhh, 9);
    // hr_out = 2*hr_feat - carafe(hr_feat, softmax9(mask_hr), 3, 1)
    carafe_s1_kernel<8><<<dim3(256/8, HH/4, NB), bm, 0, s0>>>(hr_feat, p_mhh, out_hr, 256);

    // join
    cudaStreamWaitEvent(s0, eL, 0);
}